// round 7
// baseline (speedup 1.0000x reference)
#include <cuda_runtime.h>
#include <math.h>

// ---------------- problem constants ----------------
#define BB        64
#define NN        128
#define FLAT      8192          // B*N
#define H_DIM     128
#define NODE_S    64
#define NODE_V    32
#define OUT_S     32
#define OUT_V     16
#define OUT_DIM   80
#define HIDN      128
#define NEE       512
#define EATT_N    4096
#define WN        4608
#define CUTOFF_F  5.0f
#define NORM_F    0.10206207261596575f   // 1/sqrt(96)
#define SQRT3_F   1.7320508075688772f
#define NACT_MAX  4096
#define ROWS3     32768         // B * NE
#define KWIN      64            // padded 49
#define KGIN      288           // padded 273
#define PCOLS     384           // packed bilinear input per node
#define KSPLIT    8

// ---------------- scratch (static device memory) ----------------
__device__ int   g_winner[FLAT];
__device__ int   g_active[FLAT];
__device__ int   g_posmap[FLAT];
__device__ int   g_count;
__device__ float g_win   [NACT_MAX * KWIN];
__device__ float g_gin   [NACT_MAX * KGIN];
__device__ float g_ghid  [NACT_MAX * HIDN];
__device__ float g_env   [NACT_MAX];
__device__ float g_wg1p  [KGIN * HIDN];
__device__ float g_w1p   [KWIN * HIDN];
__device__ float g_hid   [NACT_MAX * HIDN];
__device__ float g_mul   [NACT_MAX];
__device__ float g_u     [NACT_MAX * 3];
__device__ float g_P     [FLAT * PCOLS];          // 12.6 MB
__device__ float g_HdT   [BB * HIDN * NN];        // 4 MB  [b][k][n]
__device__ float g_Q     [BB * HIDN * PCOLS];     // 12.6 MB [b][k][col]
__device__ float g_Q2    [BB * PCOLS];
__device__ float g_vpart [BB * KSPLIT * OUT_DIM];
__device__ float g_vabs  [BB * OUT_DIM];
__device__ float g_scales[NEE * 48];
__device__ float g_inv   [ROWS3 * 48];
__device__ float g_x1    [ROWS3 * 128];
__device__ float g_x2    [ROWS3 * 128];

__device__ __forceinline__ float siluf(float x) { return x / (1.0f + expf(-x)); }
__device__ __forceinline__ float sigmoidf_(float x) { return 1.0f / (1.0f + expf(-x)); }

// ---------------- k_init ----------------
__global__ void k_init() {
    int i = blockIdx.x * blockDim.x + threadIdx.x;
    if (i < FLAT) g_winner[i] = -1;
    if (i == 0)   g_count = 0;
}

// ---------------- scatter: last-write-wins == max edge index ----------------
__global__ void k_scatter(const int* __restrict__ att_dst) {
    int e = blockIdx.x * blockDim.x + threadIdx.x;
    if (e < EATT_N) atomicMax(&g_winner[att_dst[e]], e);
}

__global__ void k_compact() {
    int i = blockIdx.x * blockDim.x + threadIdx.x;
    if (i < FLAT && g_winner[i] >= 0) {
        int p = atomicAdd(&g_count, 1);
        g_active[p] = i;
        g_posmap[i] = p;
    }
}

// ---------------- k_padw ----------------
__global__ void k_padw(const float* __restrict__ wg1, const float* __restrict__ w1_rad) {
    int i = blockIdx.x * blockDim.x + threadIdx.x;
    if (i < KGIN * HIDN) g_wg1p[i] = (i < 273 * HIDN) ? wg1[i] : 0.0f;
    if (i < KWIN * HIDN) g_w1p[i]  = (i < 49 * HIDN)  ? w1_rad[i] : 0.0f;
}

// ---------------- k_prep ----------------
__global__ void __launch_bounds__(128)
k_prep(const float* __restrict__ h,
       const int*   __restrict__ z,
       const int*   __restrict__ absorber_index,
       const float* __restrict__ att_dist,
       const float* __restrict__ att_vec,
       const float* __restrict__ w_zemb)
{
    const int pos = blockIdx.x;
    if (pos >= g_count) return;
    const int tid = threadIdx.x;
    const int node = g_active[pos];
    const int b = node >> 7, n = node & 127;
    const int e = g_winner[node];
    const float d = att_dist[e];
    const int absb = absorber_index[b];
    const float isabs = (n == absb) ? 1.0f : 0.0f;
    const float width = CUTOFF_F / 15.0f;
    const float invwidth = 15.0f / CUTOFF_F;

    if (tid < KWIN) {
        float v = 0.0f;
        if (tid < 32)       v = w_zemb[z[node] * 32 + tid];
        else if (tid == 32) v = isabs;
        else if (tid < 49) {
            float t = (d - (float)(tid - 33) * width) * invwidth;
            v = expf(-0.5f * t * t);
        }
        g_win[pos * KWIN + tid] = v;
    }
    g_gin[pos * KGIN + tid]       = h[(b * NN + absb) * H_DIM + tid];
    g_gin[pos * KGIN + 128 + tid] = h[node * H_DIM + tid];
    if (tid < 32) {
        float v = 0.0f;
        if (tid < 16) {
            float t = (d - (float)tid * width) * invwidth;
            v = expf(-0.5f * t * t);
        } else if (tid == 16) v = isabs;
        g_gin[pos * KGIN + 256 + tid] = v;
    }
    if (tid == 0)
        g_env[pos] = (d < CUTOFF_F) ? 0.5f * (cospif(d / CUTOFF_F) + 1.0f) : 0.0f;
    if (tid < 3)
        g_u[pos * 3 + tid] = att_vec[e * 3 + tid] / fmaxf(d, 1e-8f);
}

// ---------------- k_gate2 ----------------
__global__ void __launch_bounds__(256)
k_gate2(const float* __restrict__ wg2, const float* __restrict__ bg2)
{
    int wid = threadIdx.x >> 5, lane = threadIdx.x & 31;
    int pos = blockIdx.x * 8 + wid;
    if (pos >= g_count) return;
    float s = 0.0f;
#pragma unroll
    for (int j = 0; j < 4; j++) {
        int k = lane + 32 * j;
        s += g_ghid[pos * HIDN + k] * wg2[k];
    }
#pragma unroll
    for (int off = 16; off > 0; off >>= 1) s += __shfl_xor_sync(0xffffffffu, s, off);
    if (lane == 0)
        g_mul[pos] = sigmoidf_(s + bg2[0]) * g_env[pos] * NORM_F;
}

// ---------------- k_scatterH: hid[pos] -> HdT[b][k][n] ----------------
__global__ void __launch_bounds__(128)
k_scatterH()
{
    int pos = blockIdx.x;
    if (pos >= g_count) return;
    int node = g_active[pos];
    int b = node >> 7, n = node & 127;
    g_HdT[(b * HIDN + threadIdx.x) * NN + n] = g_hid[pos * HIDN + threadIdx.x];
}

// ---------------- k_buildP: per-node packed bilinear input ----------------
__global__ void __launch_bounds__(128)
k_buildP(const float* __restrict__ h_full)
{
    const int node = blockIdx.x;
    const int tid = threadIdx.x;
    float* Prow = g_P + (size_t)node * PCOLS;
    if (g_winner[node] < 0) {
        for (int c = tid; c < PCOLS; c += 128) Prow[c] = 0.0f;
        return;
    }
    const int pos = g_posmap[node];
    __shared__ float s1[NODE_S];
    __shared__ float v1s[NODE_V * 3];
    __shared__ float bvi[NODE_V];
    __shared__ float uu[3];
    __shared__ float smul;
    const float* hf = h_full + (size_t)node * 160;
    if (tid < NODE_S) s1[tid] = hf[tid];
    if (tid < 96) v1s[tid] = hf[NODE_S + tid];
    if (tid < 3) uu[tid] = g_u[pos * 3 + tid];
    if (tid == 127) smul = g_mul[pos];
    __syncthreads();
    if (tid < NODE_V)
        bvi[tid] = v1s[3 * tid] * uu[0] + v1s[3 * tid + 1] * uu[1] + v1s[3 * tid + 2] * uu[2];
    __syncthreads();
    const float mul = smul;
#pragma unroll
    for (int c = tid; c < PCOLS; c += 128) {
        float v;
        if (c < 64)       v = s1[c];
        else if (c < 96)  v = bvi[c - 64];
        else if (c < 288) { int cc = (c - 96) >> 6, i = (c - 96) & 63; v = SQRT3_F * uu[cc] * s1[i]; }
        else              { int cc = (c - 288) >> 5, i = (c - 288) & 31; v = v1s[i * 3 + cc]; }
        Prow[c] = mul * v;
    }
}

// ---------------- batched SGEMM (Q = HdT_b @ P_b): 64x64x16 tiles ----------------
__global__ void __launch_bounds__(256)
k_gemmQ()
{
    __shared__ __align__(16) float As[16][68];
    __shared__ __align__(16) float Ws[16][64];

    const int tid = threadIdx.x;
    const int tx = tid & 15, ty = tid >> 4;
    const int n0 = blockIdx.x * 64, m0 = blockIdx.y * 64;
    const int bz = blockIdx.z;
    const float* A = g_HdT + (size_t)bz * HIDN * NN;        // [128 k][128 n]
    const float* W = g_P   + (size_t)bz * NN * PCOLS;       // [128 n][384 col]
    float* C = g_Q + (size_t)bz * HIDN * PCOLS;
    const int arow = tid >> 2, ac4 = tid & 3;
    const int wrow = tid >> 4, wc4 = tid & 15;

    float acc[4][4];
#pragma unroll
    for (int i = 0; i < 4; i++)
#pragma unroll
        for (int j = 0; j < 4; j++) acc[i][j] = 0.0f;

    for (int k0 = 0; k0 < NN; k0 += 16) {
        float4 av = *reinterpret_cast<const float4*>(A + (m0 + arow) * NN + k0 + ac4 * 4);
        As[ac4 * 4 + 0][arow] = av.x;
        As[ac4 * 4 + 1][arow] = av.y;
        As[ac4 * 4 + 2][arow] = av.z;
        As[ac4 * 4 + 3][arow] = av.w;
        *reinterpret_cast<float4*>(&Ws[wrow][wc4 * 4]) =
            *reinterpret_cast<const float4*>(W + (k0 + wrow) * PCOLS + n0 + wc4 * 4);
        __syncthreads();
#pragma unroll
        for (int k = 0; k < 16; k++) {
            float4 a = *reinterpret_cast<const float4*>(&As[k][ty * 4]);
            float4 b = *reinterpret_cast<const float4*>(&Ws[k][tx * 4]);
            float ar[4] = {a.x, a.y, a.z, a.w};
            float br[4] = {b.x, b.y, b.z, b.w};
#pragma unroll
            for (int i = 0; i < 4; i++)
#pragma unroll
                for (int j = 0; j < 4; j++) acc[i][j] += ar[i] * br[j];
        }
        __syncthreads();
    }
#pragma unroll
    for (int i = 0; i < 4; i++) {
        float4 c = {acc[i][0], acc[i][1], acc[i][2], acc[i][3]};
        *reinterpret_cast<float4*>(C + (size_t)(m0 + ty * 4 + i) * PCOLS + n0 + tx * 4) = c;
    }
}

// ---------------- k_q2: Q2[b][col] = sum_n P ----------------
__global__ void __launch_bounds__(384)
k_q2()
{
    int b = blockIdx.x, col = threadIdx.x;
    const float* Pb = g_P + (size_t)b * NN * PCOLS;
    float s = 0.0f;
    for (int n = 0; n < NN; n++) s += Pb[n * PCOLS + col];
    g_Q2[b * PCOLS + col] = s;
}

// ---------------- k_final: contract Q with w2_rad (k-split partials) ----------
__global__ void __launch_bounds__(128)
k_final(const float* __restrict__ w2)
{
    const int b = blockIdx.x;
    const int ks = blockIdx.y * (HIDN / KSPLIT);
    const int t = threadIdx.x;
    __shared__ float qs[PCOLS];

    float a0 = 0.0f, a1 = 0.0f, a2 = 0.0f, a3 = 0.0f;
    for (int k = ks; k < ks + HIDN / KSPLIT; k++) {
        const float* qrow = g_Q + (size_t)(b * HIDN + k) * PCOLS;
        __syncthreads();
        qs[t] = qrow[t]; qs[128 + t] = qrow[128 + t]; qs[256 + t] = qrow[256 + t];
        __syncthreads();
        const float* wr = w2 + (size_t)k * WN;
        if (t < 32) {
            const int o = t;
#pragma unroll 16
            for (int i = 0; i < 64; i++) {
                float v = qs[i] * wr[i * 32 + o];
                if ((i & 3) == 0) a0 += v; else if ((i & 3) == 1) a1 += v;
                else if ((i & 3) == 2) a2 += v; else a3 += v;
            }
#pragma unroll 16
            for (int i = 0; i < 32; i++) {
                float v = qs[64 + i] * wr[2048 + i * 32 + o];
                if ((i & 3) == 0) a0 += v; else if ((i & 3) == 1) a1 += v;
                else if ((i & 3) == 2) a2 += v; else a3 += v;
            }
        } else if (t < 80) {
            const int tt = t - 32;
            const int o = tt & 15, c = tt >> 4;
#pragma unroll 16
            for (int i = 0; i < 64; i++) {
                float v = qs[96 + 64 * c + i] * wr[3072 + i * 16 + o];
                if ((i & 3) == 0) a0 += v; else if ((i & 3) == 1) a1 += v;
                else if ((i & 3) == 2) a2 += v; else a3 += v;
            }
#pragma unroll 16
            for (int i = 0; i < 32; i++) {
                float v = qs[288 + 32 * c + i] * wr[4096 + i * 16 + o];
                if ((i & 3) == 0) a0 += v; else if ((i & 3) == 1) a1 += v;
                else if ((i & 3) == 2) a2 += v; else a3 += v;
            }
        }
    }
    if (t < 80) {
        int oidx = (t < 32) ? t : (32 + ((t - 32) & 15) * 3 + ((t - 32) >> 4));
        g_vpart[(b * KSPLIT + blockIdx.y) * OUT_DIM + oidx] = (a0 + a1) + (a2 + a3);
    }
}

// ---------------- k_finred: sum partials + bias (b2_rad) term ----------------
__global__ void __launch_bounds__(80)
k_finred(const float* __restrict__ b2)
{
    const int b = blockIdx.x, j = threadIdx.x;
    float s = 0.0f;
#pragma unroll
    for (int p = 0; p < KSPLIT; p++) s += g_vpart[(b * KSPLIT + p) * OUT_DIM + j];
    const float* Q2 = g_Q2 + b * PCOLS;
    if (j < 32) {
        const int o = j;
        for (int i = 0; i < 64; i++) s += Q2[i] * b2[i * 32 + o];
        for (int i = 0; i < 32; i++) s += Q2[64 + i] * b2[2048 + i * 32 + o];
    } else {
        const int o = (j - 32) / 3, c = (j - 32) % 3;
        for (int i = 0; i < 64; i++) s += Q2[96 + 64 * c + i] * b2[3072 + i * 16 + o];
        for (int i = 0; i < 32; i++) s += Q2[288 + 32 * c + i] * b2[4096 + i * 16 + o];
    }
    g_vabs[b * OUT_DIM + j] = s;
}

// ---------------- small tiled SGEMM: 64x64x16 ----------------
__global__ void __launch_bounds__(256)
k_gemm64(const float* __restrict__ A, const float* __restrict__ W,
         const float* __restrict__ bias, float* __restrict__ C,
         int M, int N, int K, int act)
{
    __shared__ __align__(16) float As[16][68];
    __shared__ __align__(16) float Ws[16][64];

    const int tid = threadIdx.x;
    const int tx = tid & 15, ty = tid >> 4;
    const int n0 = blockIdx.x * 64, m0 = blockIdx.y * 64;
    const int arow = tid >> 2, ac4 = tid & 3;
    const int wrow = tid >> 4, wc4 = tid & 15;

    float acc[4][4];
#pragma unroll
    for (int i = 0; i < 4; i++)
#pragma unroll
        for (int j = 0; j < 4; j++) acc[i][j] = 0.0f;

    for (int k0 = 0; k0 < K; k0 += 16) {
        float4 av = *reinterpret_cast<const float4*>(A + (size_t)(m0 + arow) * K + k0 + ac4 * 4);
        As[ac4 * 4 + 0][arow] = av.x;
        As[ac4 * 4 + 1][arow] = av.y;
        As[ac4 * 4 + 2][arow] = av.z;
        As[ac4 * 4 + 3][arow] = av.w;
        *reinterpret_cast<float4*>(&Ws[wrow][wc4 * 4]) =
            *reinterpret_cast<const float4*>(W + (size_t)(k0 + wrow) * N + n0 + wc4 * 4);
        __syncthreads();
#pragma unroll
        for (int k = 0; k < 16; k++) {
            float4 a = *reinterpret_cast<const float4*>(&As[k][ty * 4]);
            float4 b = *reinterpret_cast<const float4*>(&Ws[k][tx * 4]);
            float ar[4] = {a.x, a.y, a.z, a.w};
            float br[4] = {b.x, b.y, b.z, b.w};
#pragma unroll
            for (int i = 0; i < 4; i++)
#pragma unroll
                for (int j = 0; j < 4; j++) acc[i][j] += ar[i] * br[j];
        }
        __syncthreads();
    }

    float4 bb = *reinterpret_cast<const float4*>(bias + n0 + tx * 4);
    float bv[4] = {bb.x, bb.y, bb.z, bb.w};
#pragma unroll
    for (int i = 0; i < 4; i++) {
        float cv[4];
#pragma unroll
        for (int j = 0; j < 4; j++) {
            float v = acc[i][j] + bv[j];
            if (act) v = siluf(v);
            cv[j] = v;
        }
        float4 c = {cv[0], cv[1], cv[2], cv[3]};
        *reinterpret_cast<float4*>(C + (size_t)(m0 + ty * 4 + i) * N + n0 + tx * 4) = c;
    }
}

// ---------------- big tiled SGEMM: 128x128x8, 8x8 ----------------
__global__ void __launch_bounds__(256, 2)
k_gemm128(const float* __restrict__ A, const float* __restrict__ W,
          const float* __restrict__ bias, float* __restrict__ C,
          int M, int N, int K, int act)
{
    __shared__ __align__(16) float As[8][132];
    __shared__ __align__(16) float Ws[8][128];

    const int tid = threadIdx.x;
    const int tx = tid & 15, ty = tid >> 4;
    const int n0 = blockIdx.x * 128, m0 = blockIdx.y * 128;
    const int arow = tid >> 1, aseg = tid & 1;
    const int wrow = tid >> 5, wc4 = tid & 31;

    float acc[8][8];
#pragma unroll
    for (int i = 0; i < 8; i++)
#pragma unroll
        for (int j = 0; j < 8; j++) acc[i][j] = 0.0f;

    for (int k0 = 0; k0 < K; k0 += 8) {
        float4 av = *reinterpret_cast<const float4*>(A + (size_t)(m0 + arow) * K + k0 + aseg * 4);
        As[aseg * 4 + 0][arow] = av.x;
        As[aseg * 4 + 1][arow] = av.y;
        As[aseg * 4 + 2][arow] = av.z;
        As[aseg * 4 + 3][arow] = av.w;
        *reinterpret_cast<float4*>(&Ws[wrow][wc4 * 4]) =
            *reinterpret_cast<const float4*>(W + (size_t)(k0 + wrow) * N + n0 + wc4 * 4);
        __syncthreads();
#pragma unroll
        for (int k = 0; k < 8; k++) {
            float4 a0 = *reinterpret_cast<const float4*>(&As[k][ty * 4]);
            float4 a1 = *reinterpret_cast<const float4*>(&As[k][64 + ty * 4]);
            float4 b0 = *reinterpret_cast<const float4*>(&Ws[k][tx * 4]);
            float4 b1 = *reinterpret_cast<const float4*>(&Ws[k][64 + tx * 4]);
            float ar[8] = {a0.x, a0.y, a0.z, a0.w, a1.x, a1.y, a1.z, a1.w};
            float br[8] = {b0.x, b0.y, b0.z, b0.w, b1.x, b1.y, b1.z, b1.w};
#pragma unroll
            for (int i = 0; i < 8; i++)
#pragma unroll
                for (int j = 0; j < 8; j++) acc[i][j] += ar[i] * br[j];
        }
        __syncthreads();
    }

    float4 bb0 = *reinterpret_cast<const float4*>(bias + n0 + tx * 4);
    float4 bb1 = *reinterpret_cast<const float4*>(bias + n0 + 64 + tx * 4);
    float bv[8] = {bb0.x, bb0.y, bb0.z, bb0.w, bb1.x, bb1.y, bb1.z, bb1.w};
#pragma unroll
    for (int i = 0; i < 8; i++) {
        int r = m0 + ((i < 4) ? (ty * 4 + i) : (64 + ty * 4 + i - 4));
        float cv[8];
#pragma unroll
        for (int j = 0; j < 8; j++) {
            float v = acc[i][j] + bv[j];
            if (act) v = siluf(v);
            cv[j] = v;
        }
        float4 c0 = {cv[0], cv[1], cv[2], cv[3]};
        float4 c1 = {cv[4], cv[5], cv[6], cv[7]};
        *reinterpret_cast<float4*>(C + (size_t)r * N + n0 + tx * 4) = c0;
        *reinterpret_cast<float4*>(C + (size_t)r * N + n0 + 64 + tx * 4) = c1;
    }
}

// ---------------- k_scales ----------------
__global__ void __launch_bounds__(128)
k_scales(const float* __restrict__ e_feat,
         const float* __restrict__ we1, const float* __restrict__ be1,
         const float* __restrict__ we2, const float* __restrict__ be2)
{
    __shared__ float hid[HIDN];
    int e = blockIdx.x, tid = threadIdx.x;
    float acc = be1[tid];
    for (int k = 0; k < 16; k++) acc += e_feat[e * 16 + k] * we1[k * HIDN + tid];
    hid[tid] = siluf(acc);
    __syncthreads();
    if (tid < 48) {
        float s = be2[tid];
        for (int k = 0; k < HIDN; k++) s += hid[k] * we2[k * 48 + tid];
        g_scales[e * 48 + tid] = s;
    }
}

// ---------------- k_inv ----------------
__global__ void __launch_bounds__(192)
k_inv()
{
    int row = blockIdx.x * 4 + threadIdx.x / 48;
    int j = threadIdx.x % 48;
    if (row >= ROWS3) return;
    int b = row >> 9, e = row & 511;
    float v;
    if (j < OUT_S) {
        v = g_vabs[b * OUT_DIM + j] * g_scales[e * 48 + j];
    } else {
        int o = j - OUT_S;
        float s = g_scales[e * 48 + OUT_S + o];
        float x0 = g_vabs[b * OUT_DIM + OUT_S + o * 3 + 0] * s;
        float x1 = g_vabs[b * OUT_DIM + OUT_S + o * 3 + 1] * s;
        float x2 = g_vabs[b * OUT_DIM + OUT_S + o * 3 + 2] * s;
        v = sqrtf(x0 * x0 + x1 * x1 + x2 * x2 + 1e-12f);
    }
    g_inv[(size_t)row * 48 + j] = v;
}

// ---------------- launch ----------------
extern "C" void kernel_launch(void* const* d_in, const int* in_sizes, int n_in,
                              void* d_out, int out_size)
{
    const float* h        = (const float*)d_in[0];
    const float* h_full   = (const float*)d_in[1];
    const int*   z        = (const int*)  d_in[2];
    const float* e_feat   = (const float*)d_in[4];
    const int*   abs_idx  = (const int*)  d_in[5];
    const int*   att_dst  = (const int*)  d_in[6];
    const float* att_dist = (const float*)d_in[7];
    const float* att_vec  = (const float*)d_in[8];
    const float* w_zemb   = (const float*)d_in[9];
    const float* w1_rad   = (const float*)d_in[10];
    const float* b1_rad   = (const float*)d_in[11];
    const float* w2_rad   = (const float*)d_in[12];
    const float* b2_rad   = (const float*)d_in[13];
    const float* wg1      = (const float*)d_in[14];
    const float* bg1      = (const float*)d_in[15];
    const float* wg2      = (const float*)d_in[16];
    const float* bg2      = (const float*)d_in[17];
    const float* we1      = (const float*)d_in[18];
    const float* be1      = (const float*)d_in[19];
    const float* we2      = (const float*)d_in[20];
    const float* be2      = (const float*)d_in[21];
    const float* wo1      = (const float*)d_in[22];
    const float* bo1      = (const float*)d_in[23];
    const float* wo2      = (const float*)d_in[24];
    const float* bo2      = (const float*)d_in[25];
    const float* wo3      = (const float*)d_in[26];
    const float* bo3      = (const float*)d_in[27];
    float* out = (float*)d_out;

    float *d_win, *d_gin, *d_ghid, *d_wg1p, *d_w1p, *d_hid, *d_invp, *d_x1, *d_x2;
    cudaGetSymbolAddress((void**)&d_win,  g_win);
    cudaGetSymbolAddress((void**)&d_gin,  g_gin);
    cudaGetSymbolAddress((void**)&d_ghid, g_ghid);
    cudaGetSymbolAddress((void**)&d_wg1p, g_wg1p);
    cudaGetSymbolAddress((void**)&d_w1p,  g_w1p);
    cudaGetSymbolAddress((void**)&d_hid,  g_hid);
    cudaGetSymbolAddress((void**)&d_invp, g_inv);
    cudaGetSymbolAddress((void**)&d_x1,   g_x1);
    cudaGetSymbolAddress((void**)&d_x2,   g_x2);

    k_init<<<(FLAT + 255) / 256, 256>>>();
    k_scatter<<<(EATT_N + 255) / 256, 256>>>(att_dst);
    k_compact<<<(FLAT + 255) / 256, 256>>>();
    k_padw<<<(KGIN * HIDN + 255) / 256, 256>>>(wg1, w1_rad);
    k_prep<<<NACT_MAX, 128>>>(h, z, abs_idx, att_dist, att_vec, w_zemb);

    // gate hidden = silu(gin @ wg1p + bg1): 4096 x 128, K=288
    k_gemm64<<<dim3(2, NACT_MAX / 64), 256>>>(d_gin, d_wg1p, bg1, d_ghid, NACT_MAX, 128, KGIN, 1);
    // rad hidden = silu(win @ w1p + b1): 4096 x 128, K=64
    k_gemm64<<<dim3(2, NACT_MAX / 64), 256>>>(d_win, d_w1p, b1_rad, d_hid, NACT_MAX, 128, KWIN, 1);
    k_gate2<<<NACT_MAX / 8, 256>>>(wg2, bg2);

    // bilinear path (replaces tpw GEMM + contract + vabs)
    k_scatterH<<<NACT_MAX, 128>>>();
    k_buildP<<<FLAT, 128>>>(h_full);
    k_gemmQ<<<dim3(PCOLS / 64, HIDN / 64, BB), 256>>>();
    k_q2<<<BB, PCOLS>>>();
    k_final<<<dim3(BB, KSPLIT), 128>>>(w2_rad);
    k_finred<<<BB, 80>>>(b2_rad);

    k_scales<<<NEE, 128>>>(e_feat, we1, be1, we2, be2);
    k_inv<<<ROWS3 / 4, 192>>>();

    // tail MLP
    k_gemm128<<<dim3(1, ROWS3 / 128), 256>>>(d_invp, wo1, bo1, d_x1, ROWS3, 128, 48, 1);
    k_gemm128<<<dim3(1, ROWS3 / 128), 256>>>(d_x1, wo2, bo2, d_x2, ROWS3, 128, 128, 1);
    k_gemm128<<<dim3(2, ROWS3 / 128), 256>>>(d_x2, wo3, bo3, out, ROWS3, 256, 128, 0);
}

// round 8
// speedup vs baseline: 1.3583x; 1.3583x over previous
#include <cuda_runtime.h>
#include <math.h>
#include <stdint.h>

// ---------------- problem constants ----------------
#define BB        64
#define NN        128
#define FLAT      8192          // B*N
#define H_DIM     128
#define NODE_S    64
#define NODE_V    32
#define OUT_S     32
#define OUT_V     16
#define OUT_DIM   80
#define HIDN      128
#define NEE       512
#define EATT_N    4096
#define WN        4608
#define CUTOFF_F  5.0f
#define NORM_F    0.10206207261596575f   // 1/sqrt(96)
#define SQRT3_F   1.7320508075688772f
#define NACT_MAX  4096
#define ROWS3     32768         // B * NE
#define KWIN      64            // padded 49
#define KGIN      288           // padded 273

// ---------------- scratch (static device memory) ----------------
__device__ int   g_winner[FLAT];
__device__ int   g_active[FLAT];
__device__ int   g_count;
__device__ float g_win   [NACT_MAX * KWIN];
__device__ float g_gin   [NACT_MAX * KGIN];
__device__ float g_ghid  [NACT_MAX * HIDN];
__device__ float g_env   [NACT_MAX];
__device__ float g_wg1p  [KGIN * HIDN];
__device__ float g_w1p   [KWIN * HIDN];
__device__ float g_hid   [NACT_MAX * HIDN];
__device__ float g_mul   [NACT_MAX];
__device__ float g_u     [NACT_MAX * 3];
__device__ float g_tpw   [NACT_MAX * WN];     // 75.5 MB
__device__ float g_ve    [FLAT * OUT_DIM];
__device__ float g_vabs  [BB * OUT_DIM];
__device__ float g_scales[NEE * 48];
__device__ float g_inv   [ROWS3 * 48];
__device__ float g_x1    [ROWS3 * 128];
__device__ float g_x2    [ROWS3 * 128];

__device__ __forceinline__ float siluf(float x) { return x / (1.0f + expf(-x)); }
__device__ __forceinline__ float sigmoidf_(float x) { return 1.0f / (1.0f + expf(-x)); }

__device__ __forceinline__ uint32_t tf32_of(float x) {
    uint32_t r;
    asm("cvt.rna.tf32.f32 %0, %1;" : "=r"(r) : "f"(x));
    return r;
}

#define MMA_TF32(c, a, b)                                                        \
    asm volatile(                                                                \
        "mma.sync.aligned.m16n8k8.row.col.f32.tf32.tf32.f32 "                    \
        "{%0,%1,%2,%3},{%4,%5,%6,%7},{%8,%9},{%0,%1,%2,%3};"                     \
        : "+f"((c)[0]), "+f"((c)[1]), "+f"((c)[2]), "+f"((c)[3])                 \
        : "r"((a)[0]), "r"((a)[1]), "r"((a)[2]), "r"((a)[3]),                    \
          "r"((b)[0]), "r"((b)[1]))

// ---------------- k_init ----------------
__global__ void k_init() {
    int i = blockIdx.x * blockDim.x + threadIdx.x;
    if (i < FLAT) g_winner[i] = -1;
    if (i == 0)   g_count = 0;
    if (i < FLAT * OUT_DIM) g_ve[i] = 0.0f;
}

// ---------------- scatter: last-write-wins == max edge index ----------------
__global__ void k_scatter(const int* __restrict__ att_dst) {
    int e = blockIdx.x * blockDim.x + threadIdx.x;
    if (e < EATT_N) atomicMax(&g_winner[att_dst[e]], e);
}

__global__ void k_compact() {
    int i = blockIdx.x * blockDim.x + threadIdx.x;
    if (i < FLAT && g_winner[i] >= 0) {
        int p = atomicAdd(&g_count, 1);
        g_active[p] = i;
    }
}

// ---------------- k_padw ----------------
__global__ void k_padw(const float* __restrict__ wg1, const float* __restrict__ w1_rad) {
    int i = blockIdx.x * blockDim.x + threadIdx.x;
    if (i < KGIN * HIDN) g_wg1p[i] = (i < 273 * HIDN) ? wg1[i] : 0.0f;
    if (i < KWIN * HIDN) g_w1p[i]  = (i < 49 * HIDN)  ? w1_rad[i] : 0.0f;
}

// ---------------- k_prep ----------------
__global__ void __launch_bounds__(128)
k_prep(const float* __restrict__ h,
       const int*   __restrict__ z,
       const int*   __restrict__ absorber_index,
       const float* __restrict__ att_dist,
       const float* __restrict__ att_vec,
       const float* __restrict__ w_zemb)
{
    const int pos = blockIdx.x;
    if (pos >= g_count) return;
    const int tid = threadIdx.x;
    const int node = g_active[pos];
    const int b = node >> 7, n = node & 127;
    const int e = g_winner[node];
    const float d = att_dist[e];
    const int absb = absorber_index[b];
    const float isabs = (n == absb) ? 1.0f : 0.0f;
    const float width = CUTOFF_F / 15.0f;
    const float invwidth = 15.0f / CUTOFF_F;

    if (tid < KWIN) {
        float v = 0.0f;
        if (tid < 32)       v = w_zemb[z[node] * 32 + tid];
        else if (tid == 32) v = isabs;
        else if (tid < 49) {
            float t = (d - (float)(tid - 33) * width) * invwidth;
            v = expf(-0.5f * t * t);
        }
        g_win[pos * KWIN + tid] = v;
    }
    g_gin[pos * KGIN + tid]       = h[(b * NN + absb) * H_DIM + tid];
    g_gin[pos * KGIN + 128 + tid] = h[node * H_DIM + tid];
    if (tid < 32) {
        float v = 0.0f;
        if (tid < 16) {
            float t = (d - (float)tid * width) * invwidth;
            v = expf(-0.5f * t * t);
        } else if (tid == 16) v = isabs;
        g_gin[pos * KGIN + 256 + tid] = v;
    }
    if (tid == 0)
        g_env[pos] = (d < CUTOFF_F) ? 0.5f * (cospif(d / CUTOFF_F) + 1.0f) : 0.0f;
    if (tid < 3)
        g_u[pos * 3 + tid] = att_vec[e * 3 + tid] / fmaxf(d, 1e-8f);
}

// ---------------- k_gate2 ----------------
__global__ void __launch_bounds__(256)
k_gate2(const float* __restrict__ wg2, const float* __restrict__ bg2)
{
    int wid = threadIdx.x >> 5, lane = threadIdx.x & 31;
    int pos = blockIdx.x * 8 + wid;
    if (pos >= g_count) return;
    float s = 0.0f;
#pragma unroll
    for (int j = 0; j < 4; j++) {
        int k = lane + 32 * j;
        s += g_ghid[pos * HIDN + k] * wg2[k];
    }
#pragma unroll
    for (int off = 16; off > 0; off >>= 1) s += __shfl_xor_sync(0xffffffffu, s, off);
    if (lane == 0)
        g_mul[pos] = sigmoidf_(s + bg2[0]) * g_env[pos] * NORM_F;
}

// ================= split-tf32 tensor-core GEMM =================
// C = act(A(MxK) @ W(KxN) + bias). Block tile 128x64, BK=16, 256 threads.
// 8 warps in 4(m) x 2(n) grid, each warp computes 32x32 via m16n8k8 MMA.
// Split precision: A = Ah + Al, B = Bh + Bl (tf32 each);
// D = Ah*Bh + Ah*Bl + Al*Bh  (error ~2^-22, fp32-class).
// Requires: M % 128 == 0, N % 64 == 0, K % 16 == 0.
#define SA 136   // smem stride for A tiles (k-major): bank-conflict free
#define SB 72    // smem stride for B tiles

__global__ void __launch_bounds__(256, 2)
k_tmma(const float* __restrict__ A, const float* __restrict__ W,
       const float* __restrict__ bias, float* __restrict__ C,
       int M, int N, int K, int act)
{
    __shared__ uint32_t sAh[16 * SA];
    __shared__ uint32_t sAl[16 * SA];
    __shared__ uint32_t sWh[16 * SB];
    __shared__ uint32_t sWl[16 * SB];

    const int tid = threadIdx.x;
    const int wid = tid >> 5, lane = tid & 31;
    const int wm = wid & 3, wn = wid >> 2;       // warp grid 4x2
    const int g = lane >> 2, tig = lane & 3;
    const int m0 = blockIdx.y * 128, n0 = blockIdx.x * 64;

    float cacc[2][4][4];
#pragma unroll
    for (int mt = 0; mt < 2; mt++)
#pragma unroll
        for (int nt = 0; nt < 4; nt++)
#pragma unroll
            for (int i = 0; i < 4; i++) cacc[mt][nt][i] = 0.0f;

    for (int k0 = 0; k0 < K; k0 += 16) {
        // ---- stage A tile 128 rows x 16 k, split into hi/lo, store k-major ----
#pragma unroll
        for (int it = 0; it < 2; it++) {
            int idx = tid + 256 * it;
            int r = idx >> 2, c4 = (idx & 3) * 4;
            float4 v = *reinterpret_cast<const float4*>(A + (size_t)(m0 + r) * K + k0 + c4);
            float vs[4] = {v.x, v.y, v.z, v.w};
#pragma unroll
            for (int j = 0; j < 4; j++) {
                uint32_t hb = tf32_of(vs[j]);
                float hf = __uint_as_float(hb);
                uint32_t lb = tf32_of(vs[j] - hf);
                sAh[(c4 + j) * SA + r] = hb;
                sAl[(c4 + j) * SA + r] = lb;
            }
        }
        // ---- stage W tile 16 k x 64 n ----
        {
            int kr = tid >> 4, nc = (tid & 15) * 4;
            float4 v = *reinterpret_cast<const float4*>(W + (size_t)(k0 + kr) * N + n0 + nc);
            float vs[4] = {v.x, v.y, v.z, v.w};
            uint32_t hb[4], lb[4];
#pragma unroll
            for (int j = 0; j < 4; j++) {
                hb[j] = tf32_of(vs[j]);
                lb[j] = tf32_of(vs[j] - __uint_as_float(hb[j]));
            }
            *reinterpret_cast<uint4*>(&sWh[kr * SB + nc]) = make_uint4(hb[0], hb[1], hb[2], hb[3]);
            *reinterpret_cast<uint4*>(&sWl[kr * SB + nc]) = make_uint4(lb[0], lb[1], lb[2], lb[3]);
        }
        __syncthreads();

#pragma unroll
        for (int ks = 0; ks < 2; ks++) {
            const int kb = ks * 8;
            uint32_t Ah[2][4], Al[2][4];
#pragma unroll
            for (int mt = 0; mt < 2; mt++) {
                int mr = wm * 32 + mt * 16;
                Ah[mt][0] = sAh[(kb + tig) * SA + mr + g];
                Ah[mt][1] = sAh[(kb + tig) * SA + mr + g + 8];
                Ah[mt][2] = sAh[(kb + tig + 4) * SA + mr + g];
                Ah[mt][3] = sAh[(kb + tig + 4) * SA + mr + g + 8];
                Al[mt][0] = sAl[(kb + tig) * SA + mr + g];
                Al[mt][1] = sAl[(kb + tig) * SA + mr + g + 8];
                Al[mt][2] = sAl[(kb + tig + 4) * SA + mr + g];
                Al[mt][3] = sAl[(kb + tig + 4) * SA + mr + g + 8];
            }
            uint32_t Bh[4][2], Bl[4][2];
#pragma unroll
            for (int nt = 0; nt < 4; nt++) {
                int nr = wn * 32 + nt * 8;
                Bh[nt][0] = sWh[(kb + tig) * SB + nr + g];
                Bh[nt][1] = sWh[(kb + tig + 4) * SB + nr + g];
                Bl[nt][0] = sWl[(kb + tig) * SB + nr + g];
                Bl[nt][1] = sWl[(kb + tig + 4) * SB + nr + g];
            }
#pragma unroll
            for (int mt = 0; mt < 2; mt++)
#pragma unroll
                for (int nt = 0; nt < 4; nt++) {
                    MMA_TF32(cacc[mt][nt], Ah[mt], Bh[nt]);
                    MMA_TF32(cacc[mt][nt], Ah[mt], Bl[nt]);
                    MMA_TF32(cacc[mt][nt], Al[mt], Bh[nt]);
                }
        }
        __syncthreads();
    }

    // ---- epilogue: bias + optional silu ----
#pragma unroll
    for (int mt = 0; mt < 2; mt++) {
        int row0 = m0 + wm * 32 + mt * 16 + g;
#pragma unroll
        for (int nt = 0; nt < 4; nt++) {
            int col = n0 + wn * 32 + nt * 8 + 2 * tig;
            float b0 = bias[col], b1 = bias[col + 1];
            float v00 = cacc[mt][nt][0] + b0;
            float v01 = cacc[mt][nt][1] + b1;
            float v10 = cacc[mt][nt][2] + b0;
            float v11 = cacc[mt][nt][3] + b1;
            if (act) { v00 = siluf(v00); v01 = siluf(v01); v10 = siluf(v10); v11 = siluf(v11); }
            float2 r0 = {v00, v01};
            float2 r1 = {v10, v11};
            *reinterpret_cast<float2*>(C + (size_t)row0 * N + col) = r0;
            *reinterpret_cast<float2*>(C + (size_t)(row0 + 8) * N + col) = r1;
        }
    }
}

// ---------------- k_contract: tpw(4608) x node tensors -> ve(80) ----------------
__global__ void __launch_bounds__(128)
k_contract(const float* __restrict__ h_full)
{
    __shared__ float s1[NODE_S];
    __shared__ float v1s[NODE_V * 3];
    __shared__ float bvi[NODE_V];
    __shared__ float uu[3];

    const int pos = blockIdx.x;
    if (pos >= g_count) return;
    const int tid = threadIdx.x;
    const int node = g_active[pos];
    const float* hf = h_full + (size_t)node * 160;

    if (tid < NODE_S) s1[tid] = hf[tid];
    if (tid < NODE_V * 3) v1s[tid] = hf[NODE_S + tid];
    if (tid < 3) uu[tid] = g_u[pos * 3 + tid];
    __syncthreads();
    if (tid < NODE_V)
        bvi[tid] = v1s[3 * tid] * uu[0] + v1s[3 * tid + 1] * uu[1] + v1s[3 * tid + 2] * uu[2];
    __syncthreads();

    const float* tp = g_tpw + (size_t)pos * WN;
    const float mul = g_mul[pos];

    if (tid < OUT_S) {
        int o = tid;
        float acc = 0.0f;
#pragma unroll 8
        for (int i = 0; i < NODE_S; i++) acc += s1[i] * tp[i * OUT_S + o];
#pragma unroll 8
        for (int i = 0; i < NODE_V; i++) acc += bvi[i] * tp[2048 + i * OUT_S + o];
        g_ve[(size_t)node * OUT_DIM + o] = acc * mul;
    }
    if (tid >= 64 && tid < 112) {
        int t = tid - 64;
        int o = t & 15, c = t >> 4;      // o<16, c<3
        float sc = 0.0f, sd = 0.0f;
#pragma unroll 8
        for (int i = 0; i < NODE_S; i++) sc += s1[i] * tp[3072 + i * OUT_V + o];
#pragma unroll 8
        for (int i = 0; i < NODE_V; i++) sd += v1s[3 * i + c] * tp[4096 + i * OUT_V + o];
        float yv = SQRT3_F * uu[c];
        g_ve[(size_t)node * OUT_DIM + OUT_S + o * 3 + c] = (sc * yv + sd) * mul;
    }
}

// ---------------- k_vabs ----------------
__global__ void k_vabs() {
    int b = blockIdx.x, t = threadIdx.x;
    if (t >= OUT_DIM) return;
    float acc = 0.0f;
    for (int n = 0; n < NN; n++)
        acc += g_ve[(size_t)(b * NN + n) * OUT_DIM + t];
    g_vabs[b * OUT_DIM + t] = acc;
}

// ---------------- k_scales ----------------
__global__ void __launch_bounds__(128)
k_scales(const float* __restrict__ e_feat,
         const float* __restrict__ we1, const float* __restrict__ be1,
         const float* __restrict__ we2, const float* __restrict__ be2)
{
    __shared__ float hid[HIDN];
    int e = blockIdx.x, tid = threadIdx.x;
    float acc = be1[tid];
    for (int k = 0; k < 16; k++) acc += e_feat[e * 16 + k] * we1[k * HIDN + tid];
    hid[tid] = siluf(acc);
    __syncthreads();
    if (tid < 48) {
        float s = be2[tid];
        for (int k = 0; k < HIDN; k++) s += hid[k] * we2[k * 48 + tid];
        g_scales[e * 48 + tid] = s;
    }
}

// ---------------- k_inv ----------------
__global__ void __launch_bounds__(192)
k_inv()
{
    int row = blockIdx.x * 4 + threadIdx.x / 48;
    int j = threadIdx.x % 48;
    if (row >= ROWS3) return;
    int b = row >> 9, e = row & 511;
    float v;
    if (j < OUT_S) {
        v = g_vabs[b * OUT_DIM + j] * g_scales[e * 48 + j];
    } else {
        int o = j - OUT_S;
        float s = g_scales[e * 48 + OUT_S + o];
        float x0 = g_vabs[b * OUT_DIM + OUT_S + o * 3 + 0] * s;
        float x1 = g_vabs[b * OUT_DIM + OUT_S + o * 3 + 1] * s;
        float x2 = g_vabs[b * OUT_DIM + OUT_S + o * 3 + 2] * s;
        v = sqrtf(x0 * x0 + x1 * x1 + x2 * x2 + 1e-12f);
    }
    g_inv[(size_t)row * 48 + j] = v;
}

// ---------------- launch ----------------
extern "C" void kernel_launch(void* const* d_in, const int* in_sizes, int n_in,
                              void* d_out, int out_size)
{
    const float* h        = (const float*)d_in[0];
    const float* h_full   = (const float*)d_in[1];
    const int*   z        = (const int*)  d_in[2];
    const float* e_feat   = (const float*)d_in[4];
    const int*   abs_idx  = (const int*)  d_in[5];
    const int*   att_dst  = (const int*)  d_in[6];
    const float* att_dist = (const float*)d_in[7];
    const float* att_vec  = (const float*)d_in[8];
    const float* w_zemb   = (const float*)d_in[9];
    const float* w1_rad   = (const float*)d_in[10];
    const float* b1_rad   = (const float*)d_in[11];
    const float* w2_rad   = (const float*)d_in[12];
    const float* b2_rad   = (const float*)d_in[13];
    const float* wg1      = (const float*)d_in[14];
    const float* bg1      = (const float*)d_in[15];
    const float* wg2      = (const float*)d_in[16];
    const float* bg2      = (const float*)d_in[17];
    const float* we1      = (const float*)d_in[18];
    const float* be1      = (const float*)d_in[19];
    const float* we2      = (const float*)d_in[20];
    const float* be2      = (const float*)d_in[21];
    const float* wo1      = (const float*)d_in[22];
    const float* bo1      = (const float*)d_in[23];
    const float* wo2      = (const float*)d_in[24];
    const float* bo2      = (const float*)d_in[25];
    const float* wo3      = (const float*)d_in[26];
    const float* bo3      = (const float*)d_in[27];
    float* out = (float*)d_out;

    float *d_win, *d_gin, *d_ghid, *d_wg1p, *d_w1p, *d_hid, *d_tpw, *d_invp, *d_x1, *d_x2;
    cudaGetSymbolAddress((void**)&d_win,  g_win);
    cudaGetSymbolAddress((void**)&d_gin,  g_gin);
    cudaGetSymbolAddress((void**)&d_ghid, g_ghid);
    cudaGetSymbolAddress((void**)&d_wg1p, g_wg1p);
    cudaGetSymbolAddress((void**)&d_w1p,  g_w1p);
    cudaGetSymbolAddress((void**)&d_hid,  g_hid);
    cudaGetSymbolAddress((void**)&d_tpw,  g_tpw);
    cudaGetSymbolAddress((void**)&d_invp, g_inv);
    cudaGetSymbolAddress((void**)&d_x1,   g_x1);
    cudaGetSymbolAddress((void**)&d_x2,   g_x2);

    k_init<<<(FLAT * OUT_DIM + 255) / 256, 256>>>();
    k_scatter<<<(EATT_N + 255) / 256, 256>>>(att_dst);
    k_compact<<<(FLAT + 255) / 256, 256>>>();
    k_padw<<<(KGIN * HIDN + 255) / 256, 256>>>(wg1, w1_rad);
    k_prep<<<NACT_MAX, 128>>>(h, z, abs_idx, att_dist, att_vec, w_zemb);

    // gate hidden = silu(gin @ wg1p + bg1): 4096 x 128, K=288
    k_tmma<<<dim3(128 / 64, NACT_MAX / 128), 256>>>(d_gin, d_wg1p, bg1, d_ghid, NACT_MAX, 128, KGIN, 1);
    // rad hidden = silu(win @ w1p + b1): 4096 x 128, K=64
    k_tmma<<<dim3(128 / 64, NACT_MAX / 128), 256>>>(d_win, d_w1p, b1_rad, d_hid, NACT_MAX, 128, KWIN, 1);
    k_gate2<<<NACT_MAX / 8, 256>>>(wg2, bg2);

    // tpw = hid @ w2_rad + b2: 4096 x 4608, K=128
    k_tmma<<<dim3(WN / 64, NACT_MAX / 128), 256>>>(d_hid, w2_rad, b2_rad, d_tpw, NACT_MAX, WN, HIDN, 0);
    k_contract<<<NACT_MAX, 128>>>(h_full);
    k_vabs<<<BB, 128>>>();
    k_scales<<<NEE, 128>>>(e_feat, we1, be1, we2, be2);
    k_inv<<<ROWS3 / 4, 192>>>();

    // tail MLP
    k_tmma<<<dim3(128 / 64, ROWS3 / 128), 256>>>(d_invp, wo1, bo1, d_x1, ROWS3, 128, 48, 1);
    k_tmma<<<dim3(128 / 64, ROWS3 / 128), 256>>>(d_x1, wo2, bo2, d_x2, ROWS3, 128, 128, 1);
    k_tmma<<<dim3(256 / 64, ROWS3 / 128), 256>>>(d_x2, wo3, bo3, out, ROWS3, 256, 128, 0);
}

// round 9
// speedup vs baseline: 1.7337x; 1.2763x over previous
#include <cuda_runtime.h>
#include <cuda_bf16.h>
#include <math.h>
#include <stdint.h>

// ---------------- problem constants ----------------
#define BB        64
#define NN        128
#define FLAT      8192          // B*N
#define H_DIM     128
#define NODE_S    64
#define NODE_V    32
#define OUT_S     32
#define OUT_V     16
#define OUT_DIM   80
#define HIDN      128
#define NEE       512
#define EATT_N    4096
#define WN        4608
#define CUTOFF_F  5.0f
#define NORM_F    0.10206207261596575f   // 1/sqrt(96)
#define SQRT3_F   1.7320508075688772f
#define NACT_MAX  4096
#define ROWS3     32768         // B * NE
#define KWIN      64            // padded 49
#define KGIN      288           // padded 273

// ---------------- scratch (static device memory) ----------------
__device__ int   g_winner[FLAT];
__device__ int   g_active[FLAT];
__device__ int   g_count;
__device__ float g_win   [NACT_MAX * KWIN];
__device__ float g_gin   [NACT_MAX * KGIN];
__device__ float g_ghid  [NACT_MAX * HIDN];
__device__ float g_env   [NACT_MAX];
__device__ float g_wg1p  [KGIN * HIDN];
__device__ float g_w1p   [KWIN * HIDN];
__device__ float g_hid   [NACT_MAX * HIDN];
__device__ float g_mul   [NACT_MAX];
__device__ float g_u     [NACT_MAX * 3];
__device__ float g_tpw   [NACT_MAX * WN];     // 75.5 MB
__device__ float g_ve    [FLAT * OUT_DIM];
__device__ float g_vabs  [BB * OUT_DIM];
__device__ float g_scales[NEE * 48];
__device__ float g_inv   [ROWS3 * 48];
__device__ float g_x1    [ROWS3 * 128];
__device__ float g_x2    [ROWS3 * 128];

__device__ __forceinline__ float siluf(float x) { return x / (1.0f + expf(-x)); }
__device__ __forceinline__ float sigmoidf_(float x) { return 1.0f / (1.0f + expf(-x)); }

// split a pair of fp32 into hi/lo bf16x2 packed words (low half = first elem)
__device__ __forceinline__ void split2(float x, float y, uint32_t& hi, uint32_t& lo) {
    __nv_bfloat162 hh = __floats2bfloat162_rn(x, y);
    float hx = __bfloat162float(__low2bfloat16(hh));
    float hy = __bfloat162float(__high2bfloat16(hh));
    __nv_bfloat162 ll = __floats2bfloat162_rn(x - hx, y - hy);
    hi = *reinterpret_cast<uint32_t*>(&hh);
    lo = *reinterpret_cast<uint32_t*>(&ll);
}

#define MMA_BF16(c, a, b)                                                        \
    asm volatile(                                                                \
        "mma.sync.aligned.m16n8k16.row.col.f32.bf16.bf16.f32 "                   \
        "{%0,%1,%2,%3},{%4,%5,%6,%7},{%8,%9},{%0,%1,%2,%3};"                     \
        : "+f"((c)[0]), "+f"((c)[1]), "+f"((c)[2]), "+f"((c)[3])                 \
        : "r"((a)[0]), "r"((a)[1]), "r"((a)[2]), "r"((a)[3]),                    \
          "r"((b)[0]), "r"((b)[1]))

// ---------------- k_init ----------------
__global__ void k_init() {
    int i = blockIdx.x * blockDim.x + threadIdx.x;
    if (i < FLAT) g_winner[i] = -1;
    if (i == 0)   g_count = 0;
    if (i < FLAT * OUT_DIM) g_ve[i] = 0.0f;
}

// ---------------- scatter: last-write-wins == max edge index ----------------
__global__ void k_scatter(const int* __restrict__ att_dst) {
    int e = blockIdx.x * blockDim.x + threadIdx.x;
    if (e < EATT_N) atomicMax(&g_winner[att_dst[e]], e);
}

__global__ void k_compact() {
    int i = blockIdx.x * blockDim.x + threadIdx.x;
    if (i < FLAT && g_winner[i] >= 0) {
        int p = atomicAdd(&g_count, 1);
        g_active[p] = i;
    }
}

// ---------------- k_padw ----------------
__global__ void k_padw(const float* __restrict__ wg1, const float* __restrict__ w1_rad) {
    int i = blockIdx.x * blockDim.x + threadIdx.x;
    if (i < KGIN * HIDN) g_wg1p[i] = (i < 273 * HIDN) ? wg1[i] : 0.0f;
    if (i < KWIN * HIDN) g_w1p[i]  = (i < 49 * HIDN)  ? w1_rad[i] : 0.0f;
}

// ---------------- k_prep ----------------
__global__ void __launch_bounds__(128)
k_prep(const float* __restrict__ h,
       const int*   __restrict__ z,
       const int*   __restrict__ absorber_index,
       const float* __restrict__ att_dist,
       const float* __restrict__ att_vec,
       const float* __restrict__ w_zemb)
{
    const int pos = blockIdx.x;
    if (pos >= g_count) return;
    const int tid = threadIdx.x;
    const int node = g_active[pos];
    const int b = node >> 7, n = node & 127;
    const int e = g_winner[node];
    const float d = att_dist[e];
    const int absb = absorber_index[b];
    const float isabs = (n == absb) ? 1.0f : 0.0f;
    const float width = CUTOFF_F / 15.0f;
    const float invwidth = 15.0f / CUTOFF_F;

    if (tid < KWIN) {
        float v = 0.0f;
        if (tid < 32)       v = w_zemb[z[node] * 32 + tid];
        else if (tid == 32) v = isabs;
        else if (tid < 49) {
            float t = (d - (float)(tid - 33) * width) * invwidth;
            v = expf(-0.5f * t * t);
        }
        g_win[pos * KWIN + tid] = v;
    }
    g_gin[pos * KGIN + tid]       = h[(b * NN + absb) * H_DIM + tid];
    g_gin[pos * KGIN + 128 + tid] = h[node * H_DIM + tid];
    if (tid < 32) {
        float v = 0.0f;
        if (tid < 16) {
            float t = (d - (float)tid * width) * invwidth;
            v = expf(-0.5f * t * t);
        } else if (tid == 16) v = isabs;
        g_gin[pos * KGIN + 256 + tid] = v;
    }
    if (tid == 0)
        g_env[pos] = (d < CUTOFF_F) ? 0.5f * (cospif(d / CUTOFF_F) + 1.0f) : 0.0f;
    if (tid < 3)
        g_u[pos * 3 + tid] = att_vec[e * 3 + tid] / fmaxf(d, 1e-8f);
}

// ---------------- k_gate2 ----------------
__global__ void __launch_bounds__(256)
k_gate2(const float* __restrict__ wg2, const float* __restrict__ bg2)
{
    int wid = threadIdx.x >> 5, lane = threadIdx.x & 31;
    int pos = blockIdx.x * 8 + wid;
    if (pos >= g_count) return;
    float s = 0.0f;
#pragma unroll
    for (int j = 0; j < 4; j++) {
        int k = lane + 32 * j;
        s += g_ghid[pos * HIDN + k] * wg2[k];
    }
#pragma unroll
    for (int off = 16; off > 0; off >>= 1) s += __shfl_xor_sync(0xffffffffu, s, off);
    if (lane == 0)
        g_mul[pos] = sigmoidf_(s + bg2[0]) * g_env[pos] * NORM_F;
}

// ================= split-bf16 tensor-core GEMM =================
// C = act(A(MxK) @ W(KxN) + bias). Block tile 128x64, BK=16, 256 threads.
// 8 warps in 4(m) x 2(n) grid, each warp computes 32x32 via m16n8k16 bf16 MMA.
// Split precision: A = Ah + Al, B = Bh + Bl (bf16 each);
// D = Ah*Bh + Ah*Bl + Al*Bh  (rel error ~2^-17 per element).
// smem: A as [kpair 0..7][row 0..127] packed bf16x2, stride 136 (conflict-free reads)
//       W as [kpair 0..7][n 0..63]   packed bf16x2, stride 72  (conflict-free)
// Requires: M % 128 == 0, N % 64 == 0, K % 16 == 0.
#define SA 136
#define SWB 72

__global__ void __launch_bounds__(256, 2)
k_bmma(const float* __restrict__ A, const float* __restrict__ W,
       const float* __restrict__ bias, float* __restrict__ C,
       int M, int N, int K, int act)
{
    __shared__ uint32_t sAh[8 * SA];
    __shared__ uint32_t sAl[8 * SA];
    __shared__ uint32_t sWh[8 * SWB];
    __shared__ uint32_t sWl[8 * SWB];

    const int tid = threadIdx.x;
    const int wid = tid >> 5, lane = tid & 31;
    const int wm = wid & 3, wn = wid >> 2;       // warp grid 4x2
    const int g = lane >> 2, tig = lane & 3;
    const int m0 = blockIdx.y * 128, n0 = blockIdx.x * 64;

    float cacc[2][4][4];
#pragma unroll
    for (int mt = 0; mt < 2; mt++)
#pragma unroll
        for (int nt = 0; nt < 4; nt++)
#pragma unroll
            for (int i = 0; i < 4; i++) cacc[mt][nt][i] = 0.0f;

    const int ar = tid >> 1, aks8 = (tid & 1) * 8;        // A staging: row, k-offset
    const int wn_s = tid & 63, wkp0 = (tid >> 6) * 2;     // W staging: n, kpair base

    for (int k0 = 0; k0 < K; k0 += 16) {
        // ---- stage A tile: 128 rows x 16 k -> hi/lo packed kpairs ----
        {
            const float* Ap = A + (size_t)(m0 + ar) * K + k0 + aks8;
            float4 v0 = *reinterpret_cast<const float4*>(Ap);
            float4 v1 = *reinterpret_cast<const float4*>(Ap + 4);
            uint32_t hi, lo;
            int kp = aks8 >> 1;
            split2(v0.x, v0.y, hi, lo); sAh[(kp + 0) * SA + ar] = hi; sAl[(kp + 0) * SA + ar] = lo;
            split2(v0.z, v0.w, hi, lo); sAh[(kp + 1) * SA + ar] = hi; sAl[(kp + 1) * SA + ar] = lo;
            split2(v1.x, v1.y, hi, lo); sAh[(kp + 2) * SA + ar] = hi; sAl[(kp + 2) * SA + ar] = lo;
            split2(v1.z, v1.w, hi, lo); sAh[(kp + 3) * SA + ar] = hi; sAl[(kp + 3) * SA + ar] = lo;
        }
        // ---- stage W tile: 16 k x 64 n -> hi/lo packed kpairs ----
#pragma unroll
        for (int j = 0; j < 2; j++) {
            int kp = wkp0 + j;
            float x = W[(size_t)(k0 + 2 * kp) * N + n0 + wn_s];
            float y = W[(size_t)(k0 + 2 * kp + 1) * N + n0 + wn_s];
            uint32_t hi, lo;
            split2(x, y, hi, lo);
            sWh[kp * SWB + wn_s] = hi;
            sWl[kp * SWB + wn_s] = lo;
        }
        __syncthreads();

        uint32_t Ah[2][4], Al[2][4];
#pragma unroll
        for (int mt = 0; mt < 2; mt++) {
            int mr = wm * 32 + mt * 16;
            Ah[mt][0] = sAh[tig * SA + mr + g];
            Ah[mt][1] = sAh[tig * SA + mr + g + 8];
            Ah[mt][2] = sAh[(tig + 4) * SA + mr + g];
            Ah[mt][3] = sAh[(tig + 4) * SA + mr + g + 8];
            Al[mt][0] = sAl[tig * SA + mr + g];
            Al[mt][1] = sAl[tig * SA + mr + g + 8];
            Al[mt][2] = sAl[(tig + 4) * SA + mr + g];
            Al[mt][3] = sAl[(tig + 4) * SA + mr + g + 8];
        }
        uint32_t Bh[4][2], Bl[4][2];
#pragma unroll
        for (int nt = 0; nt < 4; nt++) {
            int nr = wn * 32 + nt * 8;
            Bh[nt][0] = sWh[tig * SWB + nr + g];
            Bh[nt][1] = sWh[(tig + 4) * SWB + nr + g];
            Bl[nt][0] = sWl[tig * SWB + nr + g];
            Bl[nt][1] = sWl[(tig + 4) * SWB + nr + g];
        }
#pragma unroll
        for (int mt = 0; mt < 2; mt++)
#pragma unroll
            for (int nt = 0; nt < 4; nt++) {
                MMA_BF16(cacc[mt][nt], Ah[mt], Bh[nt]);
                MMA_BF16(cacc[mt][nt], Ah[mt], Bl[nt]);
                MMA_BF16(cacc[mt][nt], Al[mt], Bh[nt]);
            }
        __syncthreads();
    }

    // ---- epilogue: bias + optional silu ----
#pragma unroll
    for (int mt = 0; mt < 2; mt++) {
        int row0 = m0 + wm * 32 + mt * 16 + g;
#pragma unroll
        for (int nt = 0; nt < 4; nt++) {
            int col = n0 + wn * 32 + nt * 8 + 2 * tig;
            float b0 = bias[col], b1 = bias[col + 1];
            float v00 = cacc[mt][nt][0] + b0;
            float v01 = cacc[mt][nt][1] + b1;
            float v10 = cacc[mt][nt][2] + b0;
            float v11 = cacc[mt][nt][3] + b1;
            if (act) { v00 = siluf(v00); v01 = siluf(v01); v10 = siluf(v10); v11 = siluf(v11); }
            float2 r0 = {v00, v01};
            float2 r1 = {v10, v11};
            *reinterpret_cast<float2*>(C + (size_t)row0 * N + col) = r0;
            *reinterpret_cast<float2*>(C + (size_t)(row0 + 8) * N + col) = r1;
        }
    }
}

// ---------------- k_contract: tpw(4608) x node tensors -> ve(80) ----------------
__global__ void __launch_bounds__(128)
k_contract(const float* __restrict__ h_full)
{
    __shared__ float s1[NODE_S];
    __shared__ float v1s[NODE_V * 3];
    __shared__ float bvi[NODE_V];
    __shared__ float uu[3];

    const int pos = blockIdx.x;
    if (pos >= g_count) return;
    const int tid = threadIdx.x;
    const int node = g_active[pos];
    const float* hf = h_full + (size_t)node * 160;

    if (tid < NODE_S) s1[tid] = hf[tid];
    if (tid < NODE_V * 3) v1s[tid] = hf[NODE_S + tid];
    if (tid < 3) uu[tid] = g_u[pos * 3 + tid];
    __syncthreads();
    if (tid < NODE_V)
        bvi[tid] = v1s[3 * tid] * uu[0] + v1s[3 * tid + 1] * uu[1] + v1s[3 * tid + 2] * uu[2];
    __syncthreads();

    const float* tp = g_tpw + (size_t)pos * WN;
    const float mul = g_mul[pos];

    if (tid < OUT_S) {
        int o = tid;
        float acc = 0.0f;
#pragma unroll 8
        for (int i = 0; i < NODE_S; i++) acc += s1[i] * tp[i * OUT_S + o];
#pragma unroll 8
        for (int i = 0; i < NODE_V; i++) acc += bvi[i] * tp[2048 + i * OUT_S + o];
        g_ve[(size_t)node * OUT_DIM + o] = acc * mul;
    }
    if (tid >= 64 && tid < 112) {
        int t = tid - 64;
        int o = t & 15, c = t >> 4;      // o<16, c<3
        float sc = 0.0f, sd = 0.0f;
#pragma unroll 8
        for (int i = 0; i < NODE_S; i++) sc += s1[i] * tp[3072 + i * OUT_V + o];
#pragma unroll 8
        for (int i = 0; i < NODE_V; i++) sd += v1s[3 * i + c] * tp[4096 + i * OUT_V + o];
        float yv = SQRT3_F * uu[c];
        g_ve[(size_t)node * OUT_DIM + OUT_S + o * 3 + c] = (sc * yv + sd) * mul;
    }
}

// ---------------- k_vabs ----------------
__global__ void k_vabs() {
    int b = blockIdx.x, t = threadIdx.x;
    if (t >= OUT_DIM) return;
    float acc = 0.0f;
    for (int n = 0; n < NN; n++)
        acc += g_ve[(size_t)(b * NN + n) * OUT_DIM + t];
    g_vabs[b * OUT_DIM + t] = acc;
}

// ---------------- k_scales ----------------
__global__ void __launch_bounds__(128)
k_scales(const float* __restrict__ e_feat,
         const float* __restrict__ we1, const float* __restrict__ be1,
         const float* __restrict__ we2, const float* __restrict__ be2)
{
    __shared__ float hid[HIDN];
    int e = blockIdx.x, tid = threadIdx.x;
    float acc = be1[tid];
    for (int k = 0; k < 16; k++) acc += e_feat[e * 16 + k] * we1[k * HIDN + tid];
    hid[tid] = siluf(acc);
    __syncthreads();
    if (tid < 48) {
        float s = be2[tid];
        for (int k = 0; k < HIDN; k++) s += hid[k] * we2[k * 48 + tid];
        g_scales[e * 48 + tid] = s;
    }
}

// ---------------- k_inv ----------------
__global__ void __launch_bounds__(192)
k_inv()
{
    int row = blockIdx.x * 4 + threadIdx.x / 48;
    int j = threadIdx.x % 48;
    if (row >= ROWS3) return;
    int b = row >> 9, e = row & 511;
    float v;
    if (j < OUT_S) {
        v = g_vabs[b * OUT_DIM + j] * g_scales[e * 48 + j];
    } else {
        int o = j - OUT_S;
        float s = g_scales[e * 48 + OUT_S + o];
        float x0 = g_vabs[b * OUT_DIM + OUT_S + o * 3 + 0] * s;
        float x1 = g_vabs[b * OUT_DIM + OUT_S + o * 3 + 1] * s;
        float x2 = g_vabs[b * OUT_DIM + OUT_S + o * 3 + 2] * s;
        v = sqrtf(x0 * x0 + x1 * x1 + x2 * x2 + 1e-12f);
    }
    g_inv[(size_t)row * 48 + j] = v;
}

// ---------------- launch ----------------
extern "C" void kernel_launch(void* const* d_in, const int* in_sizes, int n_in,
                              void* d_out, int out_size)
{
    const float* h        = (const float*)d_in[0];
    const float* h_full   = (const float*)d_in[1];
    const int*   z        = (const int*)  d_in[2];
    const float* e_feat   = (const float*)d_in[4];
    const int*   abs_idx  = (const int*)  d_in[5];
    const int*   att_dst  = (const int*)  d_in[6];
    const float* att_dist = (const float*)d_in[7];
    const float* att_vec  = (const float*)d_in[8];
    const float* w_zemb   = (const float*)d_in[9];
    const float* w1_rad   = (const float*)d_in[10];
    const float* b1_rad   = (const float*)d_in[11];
    const float* w2_rad   = (const float*)d_in[12];
    const float* b2_rad   = (const float*)d_in[13];
    const float* wg1      = (const float*)d_in[14];
    const float* bg1      = (const float*)d_in[15];
    const float* wg2      = (const float*)d_in[16];
    const float* bg2      = (const float*)d_in[17];
    const float* we1      = (const float*)d_in[18];
    const float* be1      = (const float*)d_in[19];
    const float* we2      = (const float*)d_in[20];
    const float* be2      = (const float*)d_in[21];
    const float* wo1      = (const float*)d_in[22];
    const float* bo1      = (const float*)d_in[23];
    const float* wo2      = (const float*)d_in[24];
    const float* bo2      = (const float*)d_in[25];
    const float* wo3      = (const float*)d_in[26];
    const float* bo3      = (const float*)d_in[27];
    float* out = (float*)d_out;

    float *d_win, *d_gin, *d_ghid, *d_wg1p, *d_w1p, *d_hid, *d_tpw, *d_invp, *d_x1, *d_x2;
    cudaGetSymbolAddress((void**)&d_win,  g_win);
    cudaGetSymbolAddress((void**)&d_gin,  g_gin);
    cudaGetSymbolAddress((void**)&d_ghid, g_ghid);
    cudaGetSymbolAddress((void**)&d_wg1p, g_wg1p);
    cudaGetSymbolAddress((void**)&d_w1p,  g_w1p);
    cudaGetSymbolAddress((void**)&d_hid,  g_hid);
    cudaGetSymbolAddress((void**)&d_tpw,  g_tpw);
    cudaGetSymbolAddress((void**)&d_invp, g_inv);
    cudaGetSymbolAddress((void**)&d_x1,   g_x1);
    cudaGetSymbolAddress((void**)&d_x2,   g_x2);

    k_init<<<(FLAT * OUT_DIM + 255) / 256, 256>>>();
    k_scatter<<<(EATT_N + 255) / 256, 256>>>(att_dst);
    k_compact<<<(FLAT + 255) / 256, 256>>>();
    k_padw<<<(KGIN * HIDN + 255) / 256, 256>>>(wg1, w1_rad);
    k_prep<<<NACT_MAX, 128>>>(h, z, abs_idx, att_dist, att_vec, w_zemb);

    // gate hidden = silu(gin @ wg1p + bg1): 4096 x 128, K=288
    k_bmma<<<dim3(128 / 64, NACT_MAX / 128), 256>>>(d_gin, d_wg1p, bg1, d_ghid, NACT_MAX, 128, KGIN, 1);
    // rad hidden = silu(win @ w1p + b1): 4096 x 128, K=64
    k_bmma<<<dim3(128 / 64, NACT_MAX / 128), 256>>>(d_win, d_w1p, b1_rad, d_hid, NACT_MAX, 128, KWIN, 1);
    k_gate2<<<NACT_MAX / 8, 256>>>(wg2, bg2);

    // tpw = hid @ w2_rad + b2: 4096 x 4608, K=128
    k_bmma<<<dim3(WN / 64, NACT_MAX / 128), 256>>>(d_hid, w2_rad, b2_rad, d_tpw, NACT_MAX, WN, HIDN, 0);
    k_contract<<<NACT_MAX, 128>>>(h_full);
    k_vabs<<<BB, 128>>>();
    k_scales<<<NEE, 128>>>(e_feat, we1, be1, we2, be2);
    k_inv<<<ROWS3 / 4, 192>>>();

    // tail MLP
    k_bmma<<<dim3(128 / 64, ROWS3 / 128), 256>>>(d_invp, wo1, bo1, d_x1, ROWS3, 128, 48, 1);
    k_bmma<<<dim3(128 / 64, ROWS3 / 128), 256>>>(d_x1, wo2, bo2, d_x2, ROWS3, 128, 128, 1);
    k_bmma<<<dim3(256 / 64, ROWS3 / 128), 256>>>(d_x2, wo3, bo3, out, ROWS3, 256, 128, 0);
}

// round 10
// speedup vs baseline: 1.7737x; 1.0231x over previous
#include <cuda_runtime.h>
#include <cuda_bf16.h>
#include <math.h>
#include <stdint.h>

// ---------------- problem constants ----------------
#define BB        64
#define NN        128
#define FLAT      8192          // B*N
#define H_DIM     128
#define NODE_S    64
#define NODE_V    32
#define OUT_S     32
#define OUT_V     16
#define OUT_DIM   80
#define HIDN      128
#define NEE       512
#define EATT_N    4096
#define WN        4608
#define CUTOFF_F  5.0f
#define NORM_F    0.10206207261596575f   // 1/sqrt(96)
#define SQRT3_F   1.7320508075688772f
#define NACT_MAX  4096
#define ROWS3     32768         // B * NE
#define KWIN      64            // padded 49
#define KGIN      288           // padded 273

// ---------------- scratch (static device memory) ----------------
__device__ int   g_winner[FLAT];
__device__ int   g_active[FLAT];
__device__ int   g_count;
__device__ float g_ghid  [NACT_MAX * HIDN];
__device__ float g_env   [NACT_MAX];
__device__ float g_mul   [NACT_MAX];
__device__ float g_u     [NACT_MAX * 3];
__device__ float g_tpw   [NACT_MAX * WN];     // 75.5 MB
__device__ float g_ve    [FLAT * OUT_DIM];
__device__ float g_vabs  [BB * OUT_DIM];
__device__ float g_scales[NEE * 48];

// pre-split bf16 hi/lo packed operands (u32 = bf16x2, consecutive k)
__device__ __align__(16) unsigned g_winH[NACT_MAX * (KWIN/2)];
__device__ __align__(16) unsigned g_winL[NACT_MAX * (KWIN/2)];
__device__ __align__(16) unsigned g_ginH[NACT_MAX * (KGIN/2)];
__device__ __align__(16) unsigned g_ginL[NACT_MAX * (KGIN/2)];
__device__ __align__(16) unsigned g_hidH[NACT_MAX * (HIDN/2)];
__device__ __align__(16) unsigned g_hidL[NACT_MAX * (HIDN/2)];
__device__ __align__(16) unsigned g_invH[ROWS3 * 24];
__device__ __align__(16) unsigned g_invL[ROWS3 * 24];
__device__ __align__(16) unsigned g_x1H[ROWS3 * 64];
__device__ __align__(16) unsigned g_x1L[ROWS3 * 64];
__device__ __align__(16) unsigned g_x2H[ROWS3 * 64];
__device__ __align__(16) unsigned g_x2L[ROWS3 * 64];
__device__ __align__(16) unsigned g_wg1H[(KGIN/2) * HIDN];
__device__ __align__(16) unsigned g_wg1L[(KGIN/2) * HIDN];
__device__ __align__(16) unsigned g_w1H[(KWIN/2) * HIDN];
__device__ __align__(16) unsigned g_w1L[(KWIN/2) * HIDN];
__device__ __align__(16) unsigned g_w2H[(HIDN/2) * WN];
__device__ __align__(16) unsigned g_w2L[(HIDN/2) * WN];
__device__ __align__(16) unsigned g_wo1H[24 * HIDN];
__device__ __align__(16) unsigned g_wo1L[24 * HIDN];
__device__ __align__(16) unsigned g_wo2H[64 * HIDN];
__device__ __align__(16) unsigned g_wo2L[64 * HIDN];
__device__ __align__(16) unsigned g_wo3H[64 * 256];
__device__ __align__(16) unsigned g_wo3L[64 * 256];

__device__ __forceinline__ float siluf(float x) { return x / (1.0f + expf(-x)); }
__device__ __forceinline__ float sigmoidf_(float x) { return 1.0f / (1.0f + expf(-x)); }

// split a pair of fp32 into hi/lo bf16x2 packed words (low half = first elem)
__device__ __forceinline__ void split2(float x, float y, unsigned& hi, unsigned& lo) {
    __nv_bfloat162 hh = __floats2bfloat162_rn(x, y);
    float hx = __bfloat162float(__low2bfloat16(hh));
    float hy = __bfloat162float(__high2bfloat16(hh));
    __nv_bfloat162 ll = __floats2bfloat162_rn(x - hx, y - hy);
    hi = *reinterpret_cast<unsigned*>(&hh);
    lo = *reinterpret_cast<unsigned*>(&ll);
}

#define MMA_BF16(c, a, b)                                                        \
    asm volatile(                                                                \
        "mma.sync.aligned.m16n8k16.row.col.f32.bf16.bf16.f32 "                   \
        "{%0,%1,%2,%3},{%4,%5,%6,%7},{%8,%9},{%0,%1,%2,%3};"                     \
        : "+f"((c)[0]), "+f"((c)[1]), "+f"((c)[2]), "+f"((c)[3])                 \
        : "r"((a)[0]), "r"((a)[1]), "r"((a)[2]), "r"((a)[3]),                    \
          "r"((b)[0]), "r"((b)[1]))

// ---------------- k_init ----------------
__global__ void k_init() {
    int i = blockIdx.x * blockDim.x + threadIdx.x;
    if (i < FLAT) g_winner[i] = -1;
    if (i == 0)   g_count = 0;
    if (i < FLAT * OUT_DIM) g_ve[i] = 0.0f;
}

// ---------------- scatter: last-write-wins == max edge index ----------------
__global__ void k_scatter(const int* __restrict__ att_dst) {
    int e = blockIdx.x * blockDim.x + threadIdx.x;
    if (e < EATT_N) atomicMax(&g_winner[att_dst[e]], e);
}

__global__ void k_compact() {
    int i = blockIdx.x * blockDim.x + threadIdx.x;
    if (i < FLAT && g_winner[i] >= 0) {
        int p = atomicAdd(&g_count, 1);
        g_active[p] = i;
    }
}

// ---------------- k_splitw: pre-split all weights into bf16 hi/lo ----------------
// segments: wg1(144x128) w1(32x128) w2(64x4608) wo1(24x128) wo2(64x128) wo3(64x256)
#define SEG0 18432
#define SEG1 22528
#define SEG2 317440
#define SEG3 320512
#define SEG4 328704
#define SEG5 345088
__global__ void k_splitw(const float* __restrict__ wg1, const float* __restrict__ w1,
                         const float* __restrict__ w2,  const float* __restrict__ wo1,
                         const float* __restrict__ wo2, const float* __restrict__ wo3)
{
    int i = blockIdx.x * blockDim.x + threadIdx.x;
    if (i >= SEG5) return;
    const float* src; unsigned *H, *L; int N, Kreal, li;
    if (i < SEG0)      { src = wg1; H = g_wg1H; L = g_wg1L; N = 128; Kreal = 273; li = i; }
    else if (i < SEG1) { src = w1;  H = g_w1H;  L = g_w1L;  N = 128; Kreal = 49;  li = i - SEG0; }
    else if (i < SEG2) { src = w2;  H = g_w2H;  L = g_w2L;  N = 4608; Kreal = 128; li = i - SEG1; }
    else if (i < SEG3) { src = wo1; H = g_wo1H; L = g_wo1L; N = 128; Kreal = 48;  li = i - SEG2; }
    else if (i < SEG4) { src = wo2; H = g_wo2H; L = g_wo2L; N = 128; Kreal = 128; li = i - SEG3; }
    else               { src = wo3; H = g_wo3H; L = g_wo3L; N = 256; Kreal = 128; li = i - SEG4; }
    int kp = li / N, n = li - kp * N;
    int k0 = 2 * kp;
    float x = (k0 < Kreal)     ? src[(size_t)k0 * N + n]       : 0.0f;
    float y = (k0 + 1 < Kreal) ? src[(size_t)(k0 + 1) * N + n] : 0.0f;
    unsigned hi, lo;
    split2(x, y, hi, lo);
    H[li] = hi; L[li] = lo;
}

// ---------------- k_prep: build split input rows per active node ----------------
__global__ void __launch_bounds__(128)
k_prep(const float* __restrict__ h,
       const int*   __restrict__ z,
       const int*   __restrict__ absorber_index,
       const float* __restrict__ att_dist,
       const float* __restrict__ att_vec,
       const float* __restrict__ w_zemb)
{
    const int pos = blockIdx.x;
    if (pos >= g_count) return;
    const int tid = threadIdx.x;
    const int node = g_active[pos];
    const int b = node >> 7, n = node & 127;
    const int e = g_winner[node];
    const float d = att_dist[e];
    const int absb = absorber_index[b];
    const float isabs = (n == absb) ? 1.0f : 0.0f;
    const float width = CUTOFF_F / 15.0f;
    const float invwidth = 15.0f / CUTOFF_F;
    unsigned hi, lo;

    // ---- win row (64 padded, 49 used): [zemb 32 | isabs | rbf 16 | pad] ----
    if (tid < KWIN) {
        float v = 0.0f;
        if (tid < 32)       v = w_zemb[z[node] * 32 + tid];
        else if (tid == 32) v = isabs;
        else if (tid < 49) {
            float t = (d - (float)(tid - 33) * width) * invwidth;
            v = expf(-0.5f * t * t);
        }
        float vp = __shfl_xor_sync(0xffffffffu, v, 1);
        if (!(tid & 1)) {
            split2(v, vp, hi, lo);
            g_winH[pos * 32 + (tid >> 1)] = hi;
            g_winL[pos * 32 + (tid >> 1)] = lo;
        }
    }
    // ---- gin row (288 padded, 273 used) ----
    {
        float v = h[(b * NN + absb) * H_DIM + tid];
        float vp = __shfl_xor_sync(0xffffffffu, v, 1);
        if (!(tid & 1)) {
            split2(v, vp, hi, lo);
            g_ginH[pos * 144 + (tid >> 1)] = hi;
            g_ginL[pos * 144 + (tid >> 1)] = lo;
        }
    }
    {
        float v = h[node * H_DIM + tid];
        float vp = __shfl_xor_sync(0xffffffffu, v, 1);
        if (!(tid & 1)) {
            split2(v, vp, hi, lo);
            g_ginH[pos * 144 + 64 + (tid >> 1)] = hi;
            g_ginL[pos * 144 + 64 + (tid >> 1)] = lo;
        }
    }
    if (tid < 32) {
        float v = 0.0f;
        if (tid < 16) {
            float t = (d - (float)tid * width) * invwidth;
            v = expf(-0.5f * t * t);
        } else if (tid == 16) v = isabs;
        float vp = __shfl_xor_sync(0xffffffffu, v, 1);
        if (!(tid & 1)) {
            split2(v, vp, hi, lo);
            g_ginH[pos * 144 + 128 + (tid >> 1)] = hi;
            g_ginL[pos * 144 + 128 + (tid >> 1)] = lo;
        }
    }
    if (tid == 0)
        g_env[pos] = (d < CUTOFF_F) ? 0.5f * (cospif(d / CUTOFF_F) + 1.0f) : 0.0f;
    if (tid < 3)
        g_u[pos * 3 + tid] = att_vec[e * 3 + tid] / fmaxf(d, 1e-8f);
}

// ---------------- k_gate2 ----------------
__global__ void __launch_bounds__(256)
k_gate2(const float* __restrict__ wg2, const float* __restrict__ bg2)
{
    int wid = threadIdx.x >> 5, lane = threadIdx.x & 31;
    int pos = blockIdx.x * 8 + wid;
    if (pos >= g_count) return;
    float s = 0.0f;
#pragma unroll
    for (int j = 0; j < 4; j++) {
        int k = lane + 32 * j;
        s += g_ghid[pos * HIDN + k] * wg2[k];
    }
#pragma unroll
    for (int off = 16; off > 0; off >>= 1) s += __shfl_xor_sync(0xffffffffu, s, off);
    if (lane == 0)
        g_mul[pos] = sigmoidf_(s + bg2[0]) * g_env[pos] * NORM_F;
}

// ================= split-bf16 tensor-core GEMM (pre-split operands) =============
// C = act(A @ W + bias). Block tile 128x64, BK=16, 256 threads, 8 warps 4x2,
// warp tile 32x32 via m16n8k16. D = AhBh + AhBl + AlBh.
// A operands: [M][K/2] u32; W: [K/2][N] u32. Double-buffered smem, 1 sync/iter.
// mode: 0 = f32 out, 1 = f32 + silu, 2 = split(hi/lo) + silu.
#define SA 136
#define SWB 72

__global__ void __launch_bounds__(256, 2)
k_bmma(const unsigned* __restrict__ Ah_g, const unsigned* __restrict__ Al_g,
       const unsigned* __restrict__ Wh_g, const unsigned* __restrict__ Wl_g,
       const float* __restrict__ bias,
       float* __restrict__ Cf, unsigned* __restrict__ CH, unsigned* __restrict__ CL,
       int M, int N, int K, int mode)
{
    __shared__ __align__(16) unsigned sAh[2][8 * SA];
    __shared__ __align__(16) unsigned sAl[2][8 * SA];
    __shared__ __align__(16) unsigned sWh[2][8 * SWB];
    __shared__ __align__(16) unsigned sWl[2][8 * SWB];

    const int tid = threadIdx.x;
    const int wid = tid >> 5, lane = tid & 31;
    const int wm = wid & 3, wn = wid >> 2;
    const int g = lane >> 2, tig = lane & 3;
    const int m0 = blockIdx.y * 128, n0 = blockIdx.x * 64;
    const int K2 = K >> 1;
    const int nk = K >> 4;

    const int ar = tid >> 1, akp = (tid & 1) * 4;       // A: row, kpair base
    const int wkp = tid >> 5, wn2 = (tid & 31) * 2;     // W: kpair row, n offset

    float cacc[2][4][4];
#pragma unroll
    for (int mt = 0; mt < 2; mt++)
#pragma unroll
        for (int nt = 0; nt < 4; nt++)
#pragma unroll
            for (int i = 0; i < 4; i++) cacc[mt][nt][i] = 0.0f;

    // prefetch tile 0
    uint4 pah = *reinterpret_cast<const uint4*>(Ah_g + (size_t)(m0 + ar) * K2 + akp);
    uint4 pal = *reinterpret_cast<const uint4*>(Al_g + (size_t)(m0 + ar) * K2 + akp);
    uint2 pwh = *reinterpret_cast<const uint2*>(Wh_g + (size_t)wkp * N + n0 + wn2);
    uint2 pwl = *reinterpret_cast<const uint2*>(Wl_g + (size_t)wkp * N + n0 + wn2);

    for (int it = 0; it < nk; it++) {
        const int buf = it & 1;
        // store current tile
        sAh[buf][(akp + 0) * SA + ar] = pah.x;
        sAh[buf][(akp + 1) * SA + ar] = pah.y;
        sAh[buf][(akp + 2) * SA + ar] = pah.z;
        sAh[buf][(akp + 3) * SA + ar] = pah.w;
        sAl[buf][(akp + 0) * SA + ar] = pal.x;
        sAl[buf][(akp + 1) * SA + ar] = pal.y;
        sAl[buf][(akp + 2) * SA + ar] = pal.z;
        sAl[buf][(akp + 3) * SA + ar] = pal.w;
        *reinterpret_cast<uint2*>(&sWh[buf][wkp * SWB + wn2]) = pwh;
        *reinterpret_cast<uint2*>(&sWl[buf][wkp * SWB + wn2]) = pwl;
        // prefetch next tile
        if (it + 1 < nk) {
            int kp0 = (it + 1) * 8;
            pah = *reinterpret_cast<const uint4*>(Ah_g + (size_t)(m0 + ar) * K2 + kp0 + akp);
            pal = *reinterpret_cast<const uint4*>(Al_g + (size_t)(m0 + ar) * K2 + kp0 + akp);
            pwh = *reinterpret_cast<const uint2*>(Wh_g + (size_t)(kp0 + wkp) * N + n0 + wn2);
            pwl = *reinterpret_cast<const uint2*>(Wl_g + (size_t)(kp0 + wkp) * N + n0 + wn2);
        }
        __syncthreads();

        unsigned Ah[2][4], Al[2][4];
#pragma unroll
        for (int mt = 0; mt < 2; mt++) {
            int mr = wm * 32 + mt * 16;
            Ah[mt][0] = sAh[buf][tig * SA + mr + g];
            Ah[mt][1] = sAh[buf][tig * SA + mr + g + 8];
            Ah[mt][2] = sAh[buf][(tig + 4) * SA + mr + g];
            Ah[mt][3] = sAh[buf][(tig + 4) * SA + mr + g + 8];
            Al[mt][0] = sAl[buf][tig * SA + mr + g];
            Al[mt][1] = sAl[buf][tig * SA + mr + g + 8];
            Al[mt][2] = sAl[buf][(tig + 4) * SA + mr + g];
            Al[mt][3] = sAl[buf][(tig + 4) * SA + mr + g + 8];
        }
        unsigned Bh[4][2], Bl[4][2];
#pragma unroll
        for (int nt = 0; nt < 4; nt++) {
            int nr = wn * 32 + nt * 8;
            Bh[nt][0] = sWh[buf][tig * SWB + nr + g];
            Bh[nt][1] = sWh[buf][(tig + 4) * SWB + nr + g];
            Bl[nt][0] = sWl[buf][tig * SWB + nr + g];
            Bl[nt][1] = sWl[buf][(tig + 4) * SWB + nr + g];
        }
#pragma unroll
        for (int mt = 0; mt < 2; mt++)
#pragma unroll
            for (int nt = 0; nt < 4; nt++) {
                MMA_BF16(cacc[mt][nt], Ah[mt], Bh[nt]);
                MMA_BF16(cacc[mt][nt], Ah[mt], Bl[nt]);
                MMA_BF16(cacc[mt][nt], Al[mt], Bh[nt]);
            }
    }

    // ---- epilogue ----
    const int N2 = N >> 1;
#pragma unroll
    for (int mt = 0; mt < 2; mt++) {
        int row0 = m0 + wm * 32 + mt * 16 + g;
#pragma unroll
        for (int nt = 0; nt < 4; nt++) {
            int col = n0 + wn * 32 + nt * 8 + 2 * tig;
            float b0 = bias[col], b1 = bias[col + 1];
            float v00 = cacc[mt][nt][0] + b0;
            float v01 = cacc[mt][nt][1] + b1;
            float v10 = cacc[mt][nt][2] + b0;
            float v11 = cacc[mt][nt][3] + b1;
            if (mode != 0) { v00 = siluf(v00); v01 = siluf(v01); v10 = siluf(v10); v11 = siluf(v11); }
            if (mode == 2) {
                unsigned hi, lo;
                split2(v00, v01, hi, lo);
                CH[(size_t)row0 * N2 + (col >> 1)] = hi;
                CL[(size_t)row0 * N2 + (col >> 1)] = lo;
                split2(v10, v11, hi, lo);
                CH[(size_t)(row0 + 8) * N2 + (col >> 1)] = hi;
                CL[(size_t)(row0 + 8) * N2 + (col >> 1)] = lo;
            } else {
                float2 r0 = {v00, v01};
                float2 r1 = {v10, v11};
                *reinterpret_cast<float2*>(Cf + (size_t)row0 * N + col) = r0;
                *reinterpret_cast<float2*>(Cf + (size_t)(row0 + 8) * N + col) = r1;
            }
        }
    }
}

// ---------------- k_contract: tpw(4608) x node tensors -> ve(80) ----------------
__global__ void __launch_bounds__(128)
k_contract(const float* __restrict__ h_full)
{
    __shared__ float s1[NODE_S];
    __shared__ float v1s[NODE_V * 3];
    __shared__ float bvi[NODE_V];
    __shared__ float uu[3];

    const int pos = blockIdx.x;
    if (pos >= g_count) return;
    const int tid = threadIdx.x;
    const int node = g_active[pos];
    const float* hf = h_full + (size_t)node * 160;

    if (tid < NODE_S) s1[tid] = hf[tid];
    if (tid < NODE_V * 3) v1s[tid] = hf[NODE_S + tid];
    if (tid < 3) uu[tid] = g_u[pos * 3 + tid];
    __syncthreads();
    if (tid < NODE_V)
        bvi[tid] = v1s[3 * tid] * uu[0] + v1s[3 * tid + 1] * uu[1] + v1s[3 * tid + 2] * uu[2];
    __syncthreads();

    const float* tp = g_tpw + (size_t)pos * WN;
    const float mul = g_mul[pos];

    if (tid < OUT_S) {
        int o = tid;
        float acc = 0.0f;
#pragma unroll 8
        for (int i = 0; i < NODE_S; i++) acc += s1[i] * tp[i * OUT_S + o];
#pragma unroll 8
        for (int i = 0; i < NODE_V; i++) acc += bvi[i] * tp[2048 + i * OUT_S + o];
        g_ve[(size_t)node * OUT_DIM + o] = acc * mul;
    }
    if (tid >= 64 && tid < 112) {
        int t = tid - 64;
        int o = t & 15, c = t >> 4;      // o<16, c<3
        float sc = 0.0f, sd = 0.0f;
#pragma unroll 8
        for (int i = 0; i < NODE_S; i++) sc += s1[i] * tp[3072 + i * OUT_V + o];
#pragma unroll 8
        for (int i = 0; i < NODE_V; i++) sd += v1s[3 * i + c] * tp[4096 + i * OUT_V + o];
        float yv = SQRT3_F * uu[c];
        g_ve[(size_t)node * OUT_DIM + OUT_S + o * 3 + c] = (sc * yv + sd) * mul;
    }
}

// ---------------- k_vabs ----------------
__global__ void k_vabs() {
    int b = blockIdx.x, t = threadIdx.x;
    if (t >= OUT_DIM) return;
    float acc = 0.0f;
    for (int n = 0; n < NN; n++)
        acc += g_ve[(size_t)(b * NN + n) * OUT_DIM + t];
    g_vabs[b * OUT_DIM + t] = acc;
}

// ---------------- k_scales ----------------
__global__ void __launch_bounds__(128)
k_scales(const float* __restrict__ e_feat,
         const float* __restrict__ we1, const float* __restrict__ be1,
         const float* __restrict__ we2, const float* __restrict__ be2)
{
    __shared__ float hid[HIDN];
    int e = blockIdx.x, tid = threadIdx.x;
    float acc = be1[tid];
    for (int k = 0; k < 16; k++) acc += e_feat[e * 16 + k] * we1[k * HIDN + tid];
    hid[tid] = siluf(acc);
    __syncthreads();
    if (tid < 48) {
        float s = be2[tid];
        for (int k = 0; k < HIDN; k++) s += hid[k] * we2[k * 48 + tid];
        g_scales[e * 48 + tid] = s;
    }
}

// ---------------- k_invs: build invariants, write split bf16 hi/lo directly ------
__global__ void __launch_bounds__(256)
k_invs()
{
    int t = blockIdx.x * blockDim.x + threadIdx.x;
    if (t >= ROWS3 * 24) return;
    int row = t / 24, jp = t - row * 24;
    int b = row >> 9, e = row & 511;
    float vals[2];
#pragma unroll
    for (int jj = 0; jj < 2; jj++) {
        int j = 2 * jp + jj;
        float v;
        if (j < OUT_S) {
            v = g_vabs[b * OUT_DIM + j] * g_scales[e * 48 + j];
        } else {
            int o = j - OUT_S;
            float s = g_scales[e * 48 + OUT_S + o];
            float x0 = g_vabs[b * OUT_DIM + OUT_S + o * 3 + 0] * s;
            float x1 = g_vabs[b * OUT_DIM + OUT_S + o * 3 + 1] * s;
            float x2 = g_vabs[b * OUT_DIM + OUT_S + o * 3 + 2] * s;
            v = sqrtf(x0 * x0 + x1 * x1 + x2 * x2 + 1e-12f);
        }
        vals[jj] = v;
    }
    unsigned hi, lo;
    split2(vals[0], vals[1], hi, lo);
    g_invH[row * 24 + jp] = hi;
    g_invL[row * 24 + jp] = lo;
}

// ---------------- launch ----------------
extern "C" void kernel_launch(void* const* d_in, const int* in_sizes, int n_in,
                              void* d_out, int out_size)
{
    const float* h        = (const float*)d_in[0];
    const float* h_full   = (const float*)d_in[1];
    const int*   z        = (const int*)  d_in[2];
    const float* e_feat   = (const float*)d_in[4];
    const int*   abs_idx  = (const int*)  d_in[5];
    const int*   att_dst  = (const int*)  d_in[6];
    const float* att_dist = (const float*)d_in[7];
    const float* att_vec  = (const float*)d_in[8];
    const float* w_zemb   = (const float*)d_in[9];
    const float* w1_rad   = (const float*)d_in[10];
    const float* b1_rad   = (const float*)d_in[11];
    const float* w2_rad   = (const float*)d_in[12];
    const float* b2_rad   = (const float*)d_in[13];
    const float* wg1      = (const float*)d_in[14];
    const float* bg1      = (const float*)d_in[15];
    const float* wg2      = (const float*)d_in[16];
    const float* bg2      = (const float*)d_in[17];
    const float* we1      = (const float*)d_in[18];
    const float* be1      = (const float*)d_in[19];
    const float* we2      = (const float*)d_in[20];
    const float* be2      = (const float*)d_in[21];
    const float* wo1      = (const float*)d_in[22];
    const float* bo1      = (const float*)d_in[23];
    const float* wo2      = (const float*)d_in[24];
    const float* bo2      = (const float*)d_in[25];
    const float* wo3      = (const float*)d_in[26];
    const float* bo3      = (const float*)d_in[27];
    float* out = (float*)d_out;

    float *d_ghid, *d_tpw;
    unsigned *d_winH, *d_winL, *d_ginH, *d_ginL, *d_hidH, *d_hidL;
    unsigned *d_invH, *d_invL, *d_x1H, *d_x1L, *d_x2H, *d_x2L;
    unsigned *d_wg1H, *d_wg1L, *d_w1H, *d_w1L, *d_w2H, *d_w2L;
    unsigned *d_wo1H, *d_wo1L, *d_wo2H, *d_wo2L, *d_wo3H, *d_wo3L;
    cudaGetSymbolAddress((void**)&d_ghid, g_ghid);
    cudaGetSymbolAddress((void**)&d_tpw,  g_tpw);
    cudaGetSymbolAddress((void**)&d_winH, g_winH);
    cudaGetSymbolAddress((void**)&d_winL, g_winL);
    cudaGetSymbolAddress((void**)&d_ginH, g_ginH);
    cudaGetSymbolAddress((void**)&d_ginL, g_ginL);
    cudaGetSymbolAddress((void**)&d_hidH, g_hidH);
    cudaGetSymbolAddress((void**)&d_hidL, g_hidL);
    cudaGetSymbolAddress((void**)&d_invH, g_invH);
    cudaGetSymbolAddress((void**)&d_invL, g_invL);
    cudaGetSymbolAddress((void**)&d_x1H,  g_x1H);
    cudaGetSymbolAddress((void**)&d_x1L,  g_x1L);
    cudaGetSymbolAddress((void**)&d_x2H,  g_x2H);
    cudaGetSymbolAddress((void**)&d_x2L,  g_x2L);
    cudaGetSymbolAddress((void**)&d_wg1H, g_wg1H);
    cudaGetSymbolAddress((void**)&d_wg1L, g_wg1L);
    cudaGetSymbolAddress((void**)&d_w1H,  g_w1H);
    cudaGetSymbolAddress((void**)&d_w1L,  g_w1L);
    cudaGetSymbolAddress((void**)&d_w2H,  g_w2H);
    cudaGetSymbolAddress((void**)&d_w2L,  g_w2L);
    cudaGetSymbolAddress((void**)&d_wo1H, g_wo1H);
    cudaGetSymbolAddress((void**)&d_wo1L, g_wo1L);
    cudaGetSymbolAddress((void**)&d_wo2H, g_wo2H);
    cudaGetSymbolAddress((void**)&d_wo2L, g_wo2L);
    cudaGetSymbolAddress((void**)&d_wo3H, g_wo3H);
    cudaGetSymbolAddress((void**)&d_wo3L, g_wo3L);

    k_init<<<(FLAT * OUT_DIM + 255) / 256, 256>>>();
    k_scatter<<<(EATT_N + 255) / 256, 256>>>(att_dst);
    k_compact<<<(FLAT + 255) / 256, 256>>>();
    k_splitw<<<(SEG5 + 255) / 256, 256>>>(wg1, w1_rad, w2_rad, wo1, wo2, wo3);
    k_prep<<<NACT_MAX, 128>>>(h, z, abs_idx, att_dist, att_vec, w_zemb);

    // gate hidden = silu(gin @ wg1 + bg1): 4096 x 128, K=288 -> f32
    k_bmma<<<dim3(2, NACT_MAX / 128), 256>>>(d_ginH, d_ginL, d_wg1H, d_wg1L, bg1,
                                             d_ghid, nullptr, nullptr, NACT_MAX, 128, KGIN, 1);
    // rad hidden = silu(win @ w1 + b1): 4096 x 128, K=64 -> split
    k_bmma<<<dim3(2, NACT_MAX / 128), 256>>>(d_winH, d_winL, d_w1H, d_w1L, b1_rad,
                                             nullptr, d_hidH, d_hidL, NACT_MAX, 128, KWIN, 2);
    k_gate2<<<NACT_MAX / 8, 256>>>(wg2, bg2);

    // tpw = hid @ w2 + b2: 4096 x 4608, K=128 -> f32
    k_bmma<<<dim3(WN / 64, NACT_MAX / 128), 256>>>(d_hidH, d_hidL, d_w2H, d_w2L, b2_rad,
                                                   d_tpw, nullptr, nullptr, NACT_MAX, WN, HIDN, 0);
    k_contract<<<NACT_MAX, 128>>>(h_full);
    k_vabs<<<BB, 128>>>();
    k_scales<<<NEE, 128>>>(e_feat, we1, be1, we2, be2);
    k_invs<<<(ROWS3 * 24 + 255) / 256, 256>>>();

    // tail MLP
    k_bmma<<<dim3(2, ROWS3 / 128), 256>>>(d_invH, d_invL, d_wo1H, d_wo1L, bo1,
                                          nullptr, d_x1H, d_x1L, ROWS3, 128, 48, 2);
    k_bmma<<<dim3(2, ROWS3 / 128), 256>>>(d_x1H, d_x1L, d_wo2H, d_wo2L, bo2,
                                          nullptr, d_x2H, d_x2L, ROWS3, 128, HIDN, 2);
    k_bmma<<<dim3(4, ROWS3 / 128), 256>>>(d_x2H, d_x2L, d_wo3H, d_wo3L, bo3,
                                          out, nullptr, nullptr, ROWS3, 256, HIDN, 0);
}